// round 12
// baseline (speedup 1.0000x reference)
#include <cuda_runtime.h>
#include <math.h>
#include <stdint.h>

#define SEQ 4096
#define DIM 1024
#define NH  16
#define HDIM 64

// Scratch. g_q/g_k/g_v hold tf32 bits in FRAGMENT-MAJOR per-tile layouts
// (see gemm epilogue + flash). g_att is row-major [s][d] tf32.
__device__ float g_q[NH * SEQ * HDIM];
__device__ float g_k[NH * SEQ * HDIM];
__device__ float g_v[NH * SEQ * HDIM];
__device__ float g_att[SEQ * DIM];
__device__ float g_xt[SEQ * DIM];
__device__ float g_wq[DIM * DIM];
__device__ float g_wk[DIM * DIM];
__device__ float g_wv[DIM * DIM];
__device__ float g_wo[DIM * DIM];
// split-K partials (raw fp32)
__device__ float g_p0[SEQ * DIM];
__device__ float g_p1[SEQ * DIM];
__device__ float g_m0[NH * SEQ];
__device__ float g_l0[NH * SEQ];
__device__ float g_m1[NH * SEQ];
__device__ float g_l1[NH * SEQ];

#define QSCALE (0.125f * 1.4426950408889634f)   // 1/sqrt(64) * log2(e)
#define MINIT  (-1.6e38f)
#define MMASK  (-3.2e38f)

__device__ __forceinline__ uint32_t f2t(float f) {
    uint32_t u;
    asm("cvt.rna.tf32.f32 %0, %1;" : "=r"(u) : "f"(f));
    return u;
}

__device__ __forceinline__ float ex2(float x) {
    float r;
    asm("ex2.approx.f32 %0, %1;" : "=f"(r) : "f"(x));
    return r;
}

__device__ __forceinline__ void mma8(float c[4],
    uint32_t a0, uint32_t a1, uint32_t a2, uint32_t a3,
    uint32_t b0, uint32_t b1)
{
    asm volatile(
        "mma.sync.aligned.m16n8k8.row.col.f32.tf32.tf32.f32 "
        "{%0,%1,%2,%3},{%4,%5,%6,%7},{%8,%9},{%0,%1,%2,%3};"
        : "+f"(c[0]), "+f"(c[1]), "+f"(c[2]), "+f"(c[3])
        : "r"(a0), "r"(a1), "r"(a2), "r"(a3), "r"(b0), "r"(b1));
}

__device__ __forceinline__ void cpa16(uint32_t dst_smem, const void* src) {
    asm volatile("cp.async.cg.shared.global [%0], [%1], 16;"
                 :: "r"(dst_smem), "l"(src));
}
__device__ __forceinline__ void cpa_commit() {
    asm volatile("cp.async.commit_group;");
}
template<int N>
__device__ __forceinline__ void cpa_wait() {
    asm volatile("cp.async.wait_group %0;" :: "n"(N));
}

// ---------------------------------------------------------------------------
// Convert fp32 -> tf32 bits
// ---------------------------------------------------------------------------
__global__ void cvt_tf32(const float* __restrict__ src, float* __restrict__ dst,
                         int n4)
{
    for (int i = blockIdx.x * blockDim.x + threadIdx.x; i < n4;
         i += gridDim.x * blockDim.x) {
        float4 v = ((const float4*)src)[i];
        v.x = __uint_as_float(f2t(v.x));
        v.y = __uint_as_float(f2t(v.y));
        v.z = __uint_as_float(f2t(v.z));
        v.w = __uint_as_float(f2t(v.w));
        ((float4*)dst)[i] = v;
    }
}

__global__ void cvt_tf32_w(const float* __restrict__ s0, float* __restrict__ d0,
                           const float* __restrict__ s1, float* __restrict__ d1,
                           const float* __restrict__ s2, float* __restrict__ d2,
                           const float* __restrict__ s3, float* __restrict__ d3,
                           int n4)
{
    const float* src; float* dst;
    if (blockIdx.z == 0)      { src = s0; dst = d0; }
    else if (blockIdx.z == 1) { src = s1; dst = d1; }
    else if (blockIdx.z == 2) { src = s2; dst = d2; }
    else                      { src = s3; dst = d3; }
    for (int i = blockIdx.x * blockDim.x + threadIdx.x; i < n4;
         i += gridDim.x * blockDim.x) {
        float4 v = ((const float4*)src)[i];
        v.x = __uint_as_float(f2t(v.x));
        v.y = __uint_as_float(f2t(v.y));
        v.z = __uint_as_float(f2t(v.z));
        v.w = __uint_as_float(f2t(v.w));
        ((float4*)dst)[i] = v;
    }
}

// ---------------------------------------------------------------------------
// TF32 GEMM (mma.sync), 64x64 warp tiles, 128 threads, BK=32, 3-stage
// cp.async. mode 0: plain f32 out (row-major).
// mode 1: Q -> RoPE+QSCALE, A-fragment-major per 128-row block.
// mode 2: K -> RoPE, B-fragment-major per 32-key tile.
// mode 3: V -> B-fragment-major (PV layout) per 32-key tile.
// ---------------------------------------------------------------------------
#define GBK   32
#define GSAS  36
#define GSTW  (128 * GSAS)
#define GSTB  (2 * GSTW * 4)
#define GSMEM (3 * GSTB)

__global__ void __launch_bounds__(128) gemm_tf32(
    const float* __restrict__ A,
    const float* __restrict__ W0, const float* __restrict__ W1,
    const float* __restrict__ W2,
    float* __restrict__ out0, float* __restrict__ out1,
    float* __restrict__ out2,
    const float* __restrict__ cosT, const float* __restrict__ sinT,
    int mode0)
{
    extern __shared__ uint32_t gsm[];

    const float* W; float* out; int mode;
    if (blockIdx.z == 0)      { W = W0; out = out0; mode = mode0; }
    else if (blockIdx.z == 1) { W = W1; out = out1; mode = 2; }
    else                      { W = W2; out = out2; mode = 3; }

    const int tid  = threadIdx.x;
    const int lane = tid & 31;
    const int wid  = tid >> 5;
    const int wm   = wid >> 1;
    const int wn   = wid & 1;
    const int g4   = lane >> 2;
    const int t4   = lane & 3;

    const int mBase = blockIdx.y * 128;
    const int nBase = blockIdx.x * 128;

    const uint32_t smemu = (uint32_t)__cvta_generic_to_shared(gsm);

    auto prefetch = [&](int s, int t) {
        const int koff = t * GBK;
        const uint32_t abase = smemu + s * GSTB;
        const uint32_t bbase = abase + GSTW * 4;
#pragma unroll
        for (int j = 0; j < 8; j++) {
            const int idx = tid + j * 128;
            const int r = idx >> 3, c4 = (idx & 7) << 2;
            cpa16(abase + (r * GSAS + c4) * 4, A + (size_t)(mBase + r) * DIM + koff + c4);
            cpa16(bbase + (r * GSAS + c4) * 4, W + (size_t)(nBase + r) * DIM + koff + c4);
        }
    };

    float c[4][8][4];
#pragma unroll
    for (int mt = 0; mt < 4; mt++)
#pragma unroll
        for (int nt = 0; nt < 8; nt++)
#pragma unroll
            for (int i = 0; i < 4; i++) c[mt][nt][i] = 0.f;

    const int NT = DIM / GBK;
    prefetch(0, 0); cpa_commit();
    prefetch(1, 1); cpa_commit();

    for (int t = 0; t < NT; t++) {
        if (t + 1 < NT) cpa_wait<1>(); else cpa_wait<0>();
        __syncthreads();

        if (t + 2 < NT) { prefetch((t + 2) % 3, t + 2); cpa_commit(); }

        const uint32_t* a_s = gsm + (t % 3) * (GSTB / 4);
        const uint32_t* b_s = a_s + GSTW;
#pragma unroll
        for (int ks = 0; ks < 4; ks++) {
            const int kk = ks * 8 + t4;
            uint32_t af[4][4], bf[8][2];
#pragma unroll
            for (int mt = 0; mt < 4; mt++) {
                const int r = wm * 64 + mt * 16 + g4;
                af[mt][0] = a_s[r * GSAS + kk];
                af[mt][1] = a_s[(r + 8) * GSAS + kk];
                af[mt][2] = a_s[r * GSAS + kk + 4];
                af[mt][3] = a_s[(r + 8) * GSAS + kk + 4];
            }
#pragma unroll
            for (int nt = 0; nt < 8; nt++) {
                const int r = wn * 64 + nt * 8 + g4;
                bf[nt][0] = b_s[r * GSAS + kk];
                bf[nt][1] = b_s[r * GSAS + kk + 4];
            }
#pragma unroll
            for (int mt = 0; mt < 4; mt++)
#pragma unroll
                for (int nt = 0; nt < 8; nt++)
                    mma8(c[mt][nt], af[mt][0], af[mt][1], af[mt][2], af[mt][3],
                         bf[nt][0], bf[nt][1]);
        }
    }

#pragma unroll
    for (int mt = 0; mt < 4; mt++) {
        const int r0 = mBase + wm * 64 + mt * 16 + g4;
#pragma unroll
        for (int nt = 0; nt < 8; nt++) {
            const int colg = nBase + wn * 64 + nt * 8 + (t4 << 1);
            const float* cc = c[mt][nt];
            if (mode == 0) {
                *(float2*)(out + (size_t)r0 * DIM + colg)       = make_float2(cc[0], cc[1]);
                *(float2*)(out + (size_t)(r0 + 8) * DIM + colg) = make_float2(cc[2], cc[3]);
                continue;
            }
            const int head = colg >> 6;
            const int hd   = colg & 63;
            const int f    = hd >> 1;
#pragma unroll
            for (int h = 0; h < 2; h++) {
                const int row = r0 + h * 8;
                float e = cc[h * 2 + 0], o = cc[h * 2 + 1];
                if (mode != 3) {
                    const float cth = cosT[row * 32 + f];
                    const float sth = sinT[row * 32 + f];
                    float re = e * cth - o * sth;
                    float ro = e * sth + o * cth;
                    if (mode == 1) { re *= QSCALE; ro *= QSCALE; }
                    e = re; o = ro;
                }
                if (mode == 1) {
                    // Q A-fragment-major per 128-row block
                    const int qb = row >> 7, r = row & 127;
                    const int widr = r >> 5, mhq = (r >> 4) & 1, g4r = r & 7;
                    const int rowH = (r >> 3) & 1;
                    const int kk = hd >> 3, colH = (hd >> 2) & 1, t4a = hd & 3;
                    const int s = rowH + 2 * colH;
                    float* base = out + ((size_t)head * SEQ + qb * 128) * 64
                        + (((widr * 8 + kk) * 2 + mhq) * 8 + g4r) * 16 + t4a * 4 + s;
                    base[0] = __uint_as_float(f2t(e));
                    base[4] = __uint_as_float(f2t(o));
                } else if (mode == 2) {
                    // K B-fragment-major per 32-key tile (QK layout)
                    const int t32 = row >> 5, key = row & 31;
                    const int ntk = key >> 3, g4k = key & 7;
                    const int kkk = hd >> 3, rem = hd & 7;
                    const int halfk = rem >> 2, t4a = rem & 3;
                    float* base = out + ((size_t)head * SEQ + t32 * 32) * 64
                        + kkk * 256 + halfk * 128 + (g4k * 4 + t4a) * 4 + ntk;
                    base[0] = __uint_as_float(f2t(e));
                    base[4] = __uint_as_float(f2t(o));
                } else {
                    // V B-fragment-major per 32-key tile (PV layout)
                    const int t32 = row >> 5, key = row & 31;
                    const int kkv = key >> 3, remk = key & 7;
                    const int halfv = remk >> 2, t4v = remk & 3;
                    const int ntv = hd >> 3, g4v = hd & 7;
                    const int ntg = ntv >> 2, nt4 = ntv & 3;
                    float* base = out + ((size_t)head * SEQ + t32 * 32) * 64
                        + kkv * 512 + halfv * 256 + ntg * 128 + (g4v * 4 + t4v) * 4 + nt4;
                    base[0]  = __uint_as_float(f2t(e));
                    base[16] = __uint_as_float(f2t(o));   // d+1 -> g4v+1 -> +16
                }
            }
        }
    }
}

// ---------------------------------------------------------------------------
// Split-K TF32 flash attention, fragment-major Q/K/V.
// Q: flat cp.async of pre-packed A fragments (no repack).
// K/V: flat 8KB tiles; B-fragments read as LDS.128 (conflict-free).
// ---------------------------------------------------------------------------
#define KT  32
#define SQF_W  8192                     // Q fragments: 128 rows x 64 d
#define KTILE_W 2048                    // K tile words (32x64)
#define STG_W  (2 * KTILE_W)            // stage = K + V
#define FLASH_SMEM ((SQF_W + 2 * STG_W) * (int)sizeof(uint32_t))   // 65536 B

__global__ void __launch_bounds__(128, 3) flash_split(
    const float* __restrict__ Q, const float* __restrict__ K,
    const float* __restrict__ V,
    float* __restrict__ p0, float* __restrict__ p1,
    float* __restrict__ gm0, float* __restrict__ gl0,
    float* __restrict__ gm1, float* __restrict__ gl1)
{
    extern __shared__ uint32_t fsm[];

    const int tid  = threadIdx.x;
    const int lane = tid & 31;
    const int wid  = tid >> 5;
    const int g4   = lane >> 2;
    const int t4   = lane & 3;

    const int enc  = gridDim.x - 1 - blockIdx.x;   // longest first
    const int qblk = enc >> 1;
    const int split = enc & 1;
    const int head = blockIdx.y;

    float* part = split ? p1 : p0;
    float* gm   = split ? gm1 : gm0;
    float* gl   = split ? gl1 : gl0;

    const uint32_t smemu = (uint32_t)__cvta_generic_to_shared(fsm);
    const float* Kh0 = K + (size_t)head * SEQ * HDIM;
    const float* Vh0 = V + (size_t)head * SEQ * HDIM;

    // ---- Q: flat async copy of pre-packed fragments (8192 words) ----
    {
        const float* Qh = Q + ((size_t)head * SEQ + qblk * 128) * HDIM;
#pragma unroll
        for (int j = 0; j < 16; j++) {
            const int idx = tid + j * 128;       // 0..2047 chunks
            cpa16(smemu + idx * 16, Qh + idx * 4);
        }
        cpa_commit();
    }

    auto prefetch = [&](int buf, int kb) {
        const uint32_t base = smemu + (SQF_W + buf * STG_W) * 4;
        const float* Kt = Kh0 + (size_t)kb * KTILE_W;
        const float* Vt = Vh0 + (size_t)kb * KTILE_W;
#pragma unroll
        for (int j = 0; j < 4; j++) {
            const int idx = tid + j * 128;       // 0..511 chunks
            cpa16(base + idx * 16, Kt + idx * 4);
            cpa16(base + KTILE_W * 4 + idx * 16, Vt + idx * 4);
        }
    };

    const int half = 2 * (qblk + 1);
    const int t0 = split * half;
    const int t1 = t0 + half;

    prefetch(0, t0); cpa_commit();
    prefetch(1, t0 + 1); cpa_commit();

    float o[2][8][4];
#pragma unroll
    for (int mh = 0; mh < 2; mh++)
#pragma unroll
        for (int nt = 0; nt < 8; nt++)
#pragma unroll
            for (int i = 0; i < 4; i++) o[mh][nt][i] = 0.f;

    float m[2][2], l[2][2];
#pragma unroll
    for (int mh = 0; mh < 2; mh++) {
        m[mh][0] = MINIT; m[mh][1] = MINIT;
        l[mh][0] = 0.f;   l[mh][1] = 0.f;
    }

    const int srcA = (lane & 28) | (t4 >> 1);
    const int srcB = srcA + 2;
    const bool odd = (t4 & 1);

    const uint32_t* qbase = fsm + wid * 2048 + g4 * 16 + t4 * 4;

    for (int kb = t0; kb < t1; kb++) {
        if (kb + 1 < t1) cpa_wait<1>(); else cpa_wait<0>();
        __syncthreads();

        const uint32_t* sK = fsm + SQF_W + (kb & 1) * STG_W;
        const uint32_t* sV = sK + KTILE_W;

        // ---- S = Q K^T : all operands via LDS.128 ----
        float sc[2][4][4];
#pragma unroll
        for (int mh = 0; mh < 2; mh++)
#pragma unroll
            for (int nt = 0; nt < 4; nt++)
#pragma unroll
                for (int i = 0; i < 4; i++) sc[mh][nt][i] = 0.f;

#pragma unroll
        for (int kk = 0; kk < 8; kk++) {
            const uint4 qa0 = *(const uint4*)(qbase + kk * 256);
            const uint4 qa1 = *(const uint4*)(qbase + kk * 256 + 128);
            const uint4 kb0 = *(const uint4*)(sK + kk * 256 + lane * 4);
            const uint4 kb1 = *(const uint4*)(sK + kk * 256 + 128 + lane * 4);
            const uint32_t b0a[4] = {kb0.x, kb0.y, kb0.z, kb0.w};
            const uint32_t b1a[4] = {kb1.x, kb1.y, kb1.z, kb1.w};
#pragma unroll
            for (int nt = 0; nt < 4; nt++) {
                mma8(sc[0][nt], qa0.x, qa0.y, qa0.z, qa0.w, b0a[nt], b1a[nt]);
                mma8(sc[1][nt], qa1.x, qa1.y, qa1.z, qa1.w, b0a[nt], b1a[nt]);
            }
        }

        // ---- causal mask ----
        if (kb >= 4 * qblk) {
#pragma unroll
            for (int mh = 0; mh < 2; mh++) {
                const int r0 = qblk * 128 + wid * 32 + mh * 16 + g4;
                const int r1 = r0 + 8;
#pragma unroll
                for (int nt = 0; nt < 4; nt++) {
                    const int col = kb * KT + nt * 8 + (t4 << 1);
                    if (col > r0)     sc[mh][nt][0] = MMASK;
                    if (col + 1 > r0) sc[mh][nt][1] = MMASK;
                    if (col > r1)     sc[mh][nt][2] = MMASK;
                    if (col + 1 > r1) sc[mh][nt][3] = MMASK;
                }
            }
        }

        // ---- online softmax (log2 domain) ----
        float corr[2][2];
#pragma unroll
        for (int mh = 0; mh < 2; mh++) {
            float mx0 = MMASK, mx1 = MMASK;
#pragma unroll
            for (int nt = 0; nt < 4; nt++) {
                mx0 = fmaxf(mx0, fmaxf(sc[mh][nt][0], sc[mh][nt][1]));
                mx1 = fmaxf(mx1, fmaxf(sc[mh][nt][2], sc[mh][nt][3]));
            }
            mx0 = fmaxf(mx0, __shfl_xor_sync(0xffffffffu, mx0, 1));
            mx0 = fmaxf(mx0, __shfl_xor_sync(0xffffffffu, mx0, 2));
            mx1 = fmaxf(mx1, __shfl_xor_sync(0xffffffffu, mx1, 1));
            mx1 = fmaxf(mx1, __shfl_xor_sync(0xffffffffu, mx1, 2));

            const float mn0 = fmaxf(m[mh][0], mx0);
            const float mn1 = fmaxf(m[mh][1], mx1);
            corr[mh][0] = ex2(m[mh][0] - mn0);
            corr[mh][1] = ex2(m[mh][1] - mn1);
            m[mh][0] = mn0; m[mh][1] = mn1;

            float ls0 = 0.f, ls1 = 0.f;
#pragma unroll
            for (int nt = 0; nt < 4; nt++) {
                sc[mh][nt][0] = ex2(sc[mh][nt][0] - mn0);
                sc[mh][nt][1] = ex2(sc[mh][nt][1] - mn0);
                sc[mh][nt][2] = ex2(sc[mh][nt][2] - mn1);
                sc[mh][nt][3] = ex2(sc[mh][nt][3] - mn1);
                ls0 += sc[mh][nt][0] + sc[mh][nt][1];
                ls1 += sc[mh][nt][2] + sc[mh][nt][3];
            }
            ls0 += __shfl_xor_sync(0xffffffffu, ls0, 1);
            ls0 += __shfl_xor_sync(0xffffffffu, ls0, 2);
            ls1 += __shfl_xor_sync(0xffffffffu, ls1, 1);
            ls1 += __shfl_xor_sync(0xffffffffu, ls1, 2);
            l[mh][0] = l[mh][0] * corr[mh][0] + ls0;
            l[mh][1] = l[mh][1] * corr[mh][1] + ls1;

#pragma unroll
            for (int nt = 0; nt < 8; nt++) {
                o[mh][nt][0] *= corr[mh][0]; o[mh][nt][1] *= corr[mh][0];
                o[mh][nt][2] *= corr[mh][1]; o[mh][nt][3] *= corr[mh][1];
            }
        }

        // ---- O += P V : V B-fragments via LDS.128 ----
#pragma unroll
        for (int kk = 0; kk < 4; kk++) {
            uint32_t pa[2][4];
#pragma unroll
            for (int mh = 0; mh < 2; mh++) {
                const float v0 = __shfl_sync(0xffffffffu, sc[mh][kk][0], srcA);
                const float v1 = __shfl_sync(0xffffffffu, sc[mh][kk][1], srcA);
                const float v2 = __shfl_sync(0xffffffffu, sc[mh][kk][2], srcA);
                const float v3 = __shfl_sync(0xffffffffu, sc[mh][kk][3], srcA);
                const float v4 = __shfl_sync(0xffffffffu, sc[mh][kk][0], srcB);
                const float v5 = __shfl_sync(0xffffffffu, sc[mh][kk][1], srcB);
                const float v6 = __shfl_sync(0xffffffffu, sc[mh][kk][2], srcB);
                const float v7 = __shfl_sync(0xffffffffu, sc[mh][kk][3], srcB);
                pa[mh][0] = f2t(odd ? v1 : v0);
                pa[mh][1] = f2t(odd ? v3 : v2);
                pa[mh][2] = f2t(odd ? v5 : v4);
                pa[mh][3] = f2t(odd ? v7 : v6);
            }
            const uint4 v00 = *(const uint4*)(sV + kk * 512 + lane * 4);
            const uint4 v01 = *(const uint4*)(sV + kk * 512 + 128 + lane * 4);
            const uint4 v10 = *(const uint4*)(sV + kk * 512 + 256 + lane * 4);
            const uint4 v11 = *(const uint4*)(sV + kk * 512 + 384 + lane * 4);
            const uint32_t b0a[8] = {v00.x, v00.y, v00.z, v00.w,
                                     v01.x, v01.y, v01.z, v01.w};
            const uint32_t b1a[8] = {v10.x, v10.y, v10.z, v10.w,
                                     v11.x, v11.y, v11.z, v11.w};
#pragma unroll
            for (int nt = 0; nt < 8; nt++) {
                mma8(o[0][nt], pa[0][0], pa[0][1], pa[0][2], pa[0][3], b0a[nt], b1a[nt]);
                mma8(o[1][nt], pa[1][0], pa[1][1], pa[1][2], pa[1][3], b0a[nt], b1a[nt]);
            }
        }

        __syncthreads();
        if (kb + 2 < t1) { prefetch(kb & 1, kb + 2); cpa_commit(); }
    }

    // ---- epilogue: raw partial O + (m, l) per row ----
#pragma unroll
    for (int mh = 0; mh < 2; mh++) {
        const int r0 = qblk * 128 + wid * 32 + mh * 16 + g4;
#pragma unroll
        for (int nt = 0; nt < 8; nt++) {
            const int col = head * HDIM + nt * 8 + (t4 << 1);
            *(float2*)(part + (size_t)r0 * DIM + col) =
                make_float2(o[mh][nt][0], o[mh][nt][1]);
            *(float2*)(part + (size_t)(r0 + 8) * DIM + col) =
                make_float2(o[mh][nt][2], o[mh][nt][3]);
        }
        if (t4 == 0) {
            gm[head * SEQ + r0]     = m[mh][0];
            gl[head * SEQ + r0]     = l[mh][0];
            gm[head * SEQ + r0 + 8] = m[mh][1];
            gl[head * SEQ + r0 + 8] = l[mh][1];
        }
    }
}

// ---------------------------------------------------------------------------
// Combine: att = (O0*w0 + O1*w1) / (l0*w0 + l1*w1), tf32 bits out.
// ---------------------------------------------------------------------------
__global__ void flash_combine(
    const float* __restrict__ p0, const float* __restrict__ p1,
    const float* __restrict__ gm0, const float* __restrict__ gl0,
    const float* __restrict__ gm1, const float* __restrict__ gl1,
    float* __restrict__ att)
{
    const int n4 = SEQ * DIM / 4;
    for (int i = blockIdx.x * blockDim.x + threadIdx.x; i < n4;
         i += gridDim.x * blockDim.x) {
        const int row  = i >> 8;
        const int head = (i >> 4) & 15;
        const int mli  = head * SEQ + row;
        const float m0 = gm0[mli], m1 = gm1[mli];
        const float ms = fmaxf(m0, m1);
        const float w0 = ex2(m0 - ms), w1 = ex2(m1 - ms);
        const float inv = 1.f / (gl0[mli] * w0 + gl1[mli] * w1);
        const float4 a = ((const float4*)p0)[i];
        const float4 b = ((const float4*)p1)[i];
        float4 r;
        r.x = __uint_as_float(f2t((a.x * w0 + b.x * w1) * inv));
        r.y = __uint_as_float(f2t((a.y * w0 + b.y * w1) * inv));
        r.z = __uint_as_float(f2t((a.z * w0 + b.z * w1) * inv));
        r.w = __uint_as_float(f2t((a.w * w0 + b.w * w1) * inv));
        ((float4*)att)[i] = r;
    }
}

// ---------------------------------------------------------------------------
// Launch
// ---------------------------------------------------------------------------
extern "C" void kernel_launch(void* const* d_in, const int* in_sizes, int n_in,
                              void* d_out, int out_size)
{
    const float* x    = (const float*)d_in[0];
    const float* cosT = (const float*)d_in[1];
    const float* sinT = (const float*)d_in[2];
    const float* wq   = (const float*)d_in[4];
    const float* wk   = (const float*)d_in[5];
    const float* wv   = (const float*)d_in[6];
    const float* wo   = (const float*)d_in[7];
    float* out = (float*)d_out;

    float *qp, *kp, *vp, *ap, *xt, *wqt, *wkt, *wvt, *wot;
    float *p0, *p1, *m0, *l0, *m1, *l1;
    cudaGetSymbolAddress((void**)&qp, g_q);
    cudaGetSymbolAddress((void**)&kp, g_k);
    cudaGetSymbolAddress((void**)&vp, g_v);
    cudaGetSymbolAddress((void**)&ap, g_att);
    cudaGetSymbolAddress((void**)&xt, g_xt);
    cudaGetSymbolAddress((void**)&wqt, g_wq);
    cudaGetSymbolAddress((void**)&wkt, g_wk);
    cudaGetSymbolAddress((void**)&wvt, g_wv);
    cudaGetSymbolAddress((void**)&wot, g_wo);
    cudaGetSymbolAddress((void**)&p0, g_p0);
    cudaGetSymbolAddress((void**)&p1, g_p1);
    cudaGetSymbolAddress((void**)&m0, g_m0);
    cudaGetSymbolAddress((void**)&l0, g_l0);
    cudaGetSymbolAddress((void**)&m1, g_m1);
    cudaGetSymbolAddress((void**)&l1, g_l1);

    cudaFuncSetAttribute(flash_split,
                         cudaFuncAttributeMaxDynamicSharedMemorySize, FLASH_SMEM);
    cudaFuncSetAttribute(gemm_tf32,
                         cudaFuncAttributeMaxDynamicSharedMemorySize, GSMEM);

    // Convert inputs to tf32 bits once
    cvt_tf32<<<512, 256>>>(x, xt, SEQ * DIM / 4);
    dim3 wgrid(128, 1, 4);
    cvt_tf32_w<<<wgrid, 256>>>(wq, wqt, wk, wkt, wv, wvt, wo, wot, DIM * DIM / 4);

    // Fused QKV projections, fragment-major outputs
    dim3 ggrid(DIM / 128, SEQ / 128, 3);
    gemm_tf32<<<ggrid, 128, GSMEM>>>(xt, wqt, wkt, wvt, qp, kp, vp, cosT, sinT, 1);

    // Split-K flash
    dim3 fgrid(2 * (SEQ / 128), NH);
    flash_split<<<fgrid, 128, FLASH_SMEM>>>(qp, kp, vp, p0, p1, m0, l0, m1, l1);

    flash_combine<<<1024, 256>>>(p0, p1, m0, l0, m1, l1, ap);

    // Output projection
    dim3 ogrid(DIM / 128, SEQ / 128, 1);
    gemm_tf32<<<ogrid, 128, GSMEM>>>(ap, wot, wot, wot, out, out, out, cosT, sinT, 0);
}

// round 13
// speedup vs baseline: 1.0698x; 1.0698x over previous
#include <cuda_runtime.h>
#include <math.h>
#include <stdint.h>

#define SEQ 4096
#define DIM 1024
#define NH  16
#define HDIM 64

// Scratch (tf32 bits stored as float unless noted)
__device__ float g_q[NH * SEQ * HDIM];   // [h][s][hd] tf32, pre-scaled
__device__ float g_k[NH * SEQ * HDIM];   // [h][s][hd] tf32
__device__ float g_v[NH * SEQ * HDIM];   // [h][s][hd] tf32
__device__ float g_att[SEQ * DIM];       // [s][d]     tf32 (merged)
__device__ float g_xt[SEQ * DIM];        // x as tf32
__device__ float g_wq[DIM * DIM];        // weights as tf32
__device__ float g_wk[DIM * DIM];
__device__ float g_wv[DIM * DIM];
__device__ float g_wo[DIM * DIM];
// split-K partials (raw fp32)
__device__ float g_p0[SEQ * DIM];
__device__ float g_p1[SEQ * DIM];
__device__ float g_m0[NH * SEQ];
__device__ float g_l0[NH * SEQ];
__device__ float g_m1[NH * SEQ];
__device__ float g_l1[NH * SEQ];
// merge counters (zero-init; merger resets -> replay-safe)
__device__ int g_cnt[NH * (SEQ / 128)];

#define QSCALE (0.125f * 1.4426950408889634f)   // 1/sqrt(64) * log2(e)
#define MINIT  (-1.6e38f)
#define MMASK  (-3.2e38f)
#define PCOMP  (1.000244140625f)                // 1 + 2^-12 (RZ-trunc bias comp)

__device__ __forceinline__ uint32_t f2t(float f) {
    uint32_t u;
    asm("cvt.rna.tf32.f32 %0, %1;" : "=r"(u) : "f"(f));
    return u;
}

__device__ __forceinline__ float ex2(float x) {
    float r;
    asm("ex2.approx.f32 %0, %1;" : "=f"(r) : "f"(x));
    return r;
}

__device__ __forceinline__ void mma8(float c[4],
    uint32_t a0, uint32_t a1, uint32_t a2, uint32_t a3,
    uint32_t b0, uint32_t b1)
{
    asm volatile(
        "mma.sync.aligned.m16n8k8.row.col.f32.tf32.tf32.f32 "
        "{%0,%1,%2,%3},{%4,%5,%6,%7},{%8,%9},{%0,%1,%2,%3};"
        : "+f"(c[0]), "+f"(c[1]), "+f"(c[2]), "+f"(c[3])
        : "r"(a0), "r"(a1), "r"(a2), "r"(a3), "r"(b0), "r"(b1));
}

__device__ __forceinline__ void cpa16(uint32_t dst_smem, const void* src) {
    asm volatile("cp.async.cg.shared.global [%0], [%1], 16;"
                 :: "r"(dst_smem), "l"(src));
}
__device__ __forceinline__ void cpa_commit() {
    asm volatile("cp.async.commit_group;");
}
template<int N>
__device__ __forceinline__ void cpa_wait() {
    asm volatile("cp.async.wait_group %0;" :: "n"(N));
}

// ---------------------------------------------------------------------------
// Convert fp32 -> tf32 bits
// ---------------------------------------------------------------------------
__global__ void cvt_tf32(const float* __restrict__ src, float* __restrict__ dst,
                         int n4)
{
    for (int i = blockIdx.x * blockDim.x + threadIdx.x; i < n4;
         i += gridDim.x * blockDim.x) {
        float4 v = ((const float4*)src)[i];
        v.x = __uint_as_float(f2t(v.x));
        v.y = __uint_as_float(f2t(v.y));
        v.z = __uint_as_float(f2t(v.z));
        v.w = __uint_as_float(f2t(v.w));
        ((float4*)dst)[i] = v;
    }
}

__global__ void cvt_tf32_w(const float* __restrict__ s0, float* __restrict__ d0,
                           const float* __restrict__ s1, float* __restrict__ d1,
                           const float* __restrict__ s2, float* __restrict__ d2,
                           const float* __restrict__ s3, float* __restrict__ d3,
                           int n4)
{
    const float* src; float* dst;
    if (blockIdx.z == 0)      { src = s0; dst = d0; }
    else if (blockIdx.z == 1) { src = s1; dst = d1; }
    else if (blockIdx.z == 2) { src = s2; dst = d2; }
    else                      { src = s3; dst = d3; }
    for (int i = blockIdx.x * blockDim.x + threadIdx.x; i < n4;
         i += gridDim.x * blockDim.x) {
        float4 v = ((const float4*)src)[i];
        v.x = __uint_as_float(f2t(v.x));
        v.y = __uint_as_float(f2t(v.y));
        v.z = __uint_as_float(f2t(v.z));
        v.w = __uint_as_float(f2t(v.w));
        ((float4*)dst)[i] = v;
    }
}

// ---------------------------------------------------------------------------
// TF32 GEMM (mma.sync), 64x64 warp tiles, 128 threads (2x2 warps),
// BK=32, 3-stage cp.async, ONE barrier per chunk. Coalesced epilogues.
// ---------------------------------------------------------------------------
#define GBK   32
#define GSAS  36
#define GSTW  (128 * GSAS)
#define GSTB  (2 * GSTW * 4)
#define GSMEM (3 * GSTB)

__global__ void __launch_bounds__(128) gemm_tf32(
    const float* __restrict__ A,
    const float* __restrict__ W0, const float* __restrict__ W1,
    const float* __restrict__ W2,
    float* __restrict__ out0, float* __restrict__ out1,
    float* __restrict__ out2,
    const float* __restrict__ cosT, const float* __restrict__ sinT,
    int mode0)
{
    extern __shared__ uint32_t gsm[];

    const float* W; float* out; int mode;
    if (blockIdx.z == 0)      { W = W0; out = out0; mode = mode0; }
    else if (blockIdx.z == 1) { W = W1; out = out1; mode = 2; }
    else                      { W = W2; out = out2; mode = 3; }

    const int tid  = threadIdx.x;
    const int lane = tid & 31;
    const int wid  = tid >> 5;
    const int wm   = wid >> 1;
    const int wn   = wid & 1;
    const int g4   = lane >> 2;
    const int t4   = lane & 3;

    const int mBase = blockIdx.y * 128;
    const int nBase = blockIdx.x * 128;

    const uint32_t smemu = (uint32_t)__cvta_generic_to_shared(gsm);

    auto prefetch = [&](int s, int t) {
        const int koff = t * GBK;
        const uint32_t abase = smemu + s * GSTB;
        const uint32_t bbase = abase + GSTW * 4;
#pragma unroll
        for (int j = 0; j < 8; j++) {
            const int idx = tid + j * 128;
            const int r = idx >> 3, c4 = (idx & 7) << 2;
            cpa16(abase + (r * GSAS + c4) * 4, A + (size_t)(mBase + r) * DIM + koff + c4);
            cpa16(bbase + (r * GSAS + c4) * 4, W + (size_t)(nBase + r) * DIM + koff + c4);
        }
    };

    float c[4][8][4];
#pragma unroll
    for (int mt = 0; mt < 4; mt++)
#pragma unroll
        for (int nt = 0; nt < 8; nt++)
#pragma unroll
            for (int i = 0; i < 4; i++) c[mt][nt][i] = 0.f;

    const int NT = DIM / GBK;
    prefetch(0, 0); cpa_commit();
    prefetch(1, 1); cpa_commit();

    for (int t = 0; t < NT; t++) {
        if (t + 1 < NT) cpa_wait<1>(); else cpa_wait<0>();
        __syncthreads();

        if (t + 2 < NT) { prefetch((t + 2) % 3, t + 2); cpa_commit(); }

        const uint32_t* a_s = gsm + (t % 3) * (GSTB / 4);
        const uint32_t* b_s = a_s + GSTW;
#pragma unroll
        for (int ks = 0; ks < 4; ks++) {
            const int kk = ks * 8 + t4;
            uint32_t af[4][4], bf[8][2];
#pragma unroll
            for (int mt = 0; mt < 4; mt++) {
                const int r = wm * 64 + mt * 16 + g4;
                af[mt][0] = a_s[r * GSAS + kk];
                af[mt][1] = a_s[(r + 8) * GSAS + kk];
                af[mt][2] = a_s[r * GSAS + kk + 4];
                af[mt][3] = a_s[(r + 8) * GSAS + kk + 4];
            }
#pragma unroll
            for (int nt = 0; nt < 8; nt++) {
                const int r = wn * 64 + nt * 8 + g4;
                bf[nt][0] = b_s[r * GSAS + kk];
                bf[nt][1] = b_s[r * GSAS + kk + 4];
            }
#pragma unroll
            for (int mt = 0; mt < 4; mt++)
#pragma unroll
                for (int nt = 0; nt < 8; nt++)
                    mma8(c[mt][nt], af[mt][0], af[mt][1], af[mt][2], af[mt][3],
                         bf[nt][0], bf[nt][1]);
        }
    }

#pragma unroll
    for (int mt = 0; mt < 4; mt++) {
        const int r0 = mBase + wm * 64 + mt * 16 + g4;
#pragma unroll
        for (int nt = 0; nt < 8; nt++) {
            const int colg = nBase + wn * 64 + nt * 8 + (t4 << 1);
            const float* cc = c[mt][nt];
            if (mode == 0) {
                *(float2*)(out + (size_t)r0 * DIM + colg)       = make_float2(cc[0], cc[1]);
                *(float2*)(out + (size_t)(r0 + 8) * DIM + colg) = make_float2(cc[2], cc[3]);
                continue;
            }
            const int head = colg >> 6;
            const int hd   = colg & 63;
            const int f    = hd >> 1;
#pragma unroll
            for (int h = 0; h < 2; h++) {
                const int row = r0 + h * 8;
                float e = cc[h * 2 + 0], o = cc[h * 2 + 1];
                float re = e, ro = o;
                if (mode != 3) {
                    const float cth = cosT[row * 32 + f];
                    const float sth = sinT[row * 32 + f];
                    re = e * cth - o * sth;
                    ro = e * sth + o * cth;
                    if (mode == 1) { re *= QSCALE; ro *= QSCALE; }
                }
                float* dst = out + ((size_t)head * SEQ + row) * HDIM + hd;
                dst[0] = __uint_as_float(f2t(re));
                dst[1] = __uint_as_float(f2t(ro));
            }
        }
    }
}

// ---------------------------------------------------------------------------
// Split-K TF32 flash attention with in-kernel merge (last-CTA-done).
// Each (qblk, head) -> 2 CTAs (halves of key range). Partials to global;
// the second CTA to finish merges (own O in regs + other partial) into att.
// M=32 warp tile, 32-key tiles, Q fragment-major in smem. P fed to MMA as
// raw fp32 bits (RZ truncation, mean-compensated via PCOMP at merge).
// ---------------------------------------------------------------------------
#define FP  68
#define VP  72
#define KT  32
#define SQF_W  8192
#define STAGE_W (KT * FP + KT * VP)
#define FLASH_SMEM ((SQF_W + 2 * STAGE_W) * (int)sizeof(uint32_t))

__global__ void __launch_bounds__(128, 3) flash_split(
    const float* __restrict__ Q, const float* __restrict__ K,
    const float* __restrict__ V,
    float* __restrict__ p0, float* __restrict__ p1,
    float* __restrict__ gm0, float* __restrict__ gl0,
    float* __restrict__ gm1, float* __restrict__ gl1,
    float* __restrict__ att)
{
    extern __shared__ uint32_t fsm[];
    uint32_t* sQf = fsm;

    const int tid  = threadIdx.x;
    const int lane = tid & 31;
    const int wid  = tid >> 5;
    const int g4   = lane >> 2;
    const int t4   = lane & 3;

    const int enc  = gridDim.x - 1 - blockIdx.x;   // longest first
    const int qblk = enc >> 1;
    const int split = enc & 1;
    const int head = blockIdx.y;

    float* part = split ? p1 : p0;
    float* gm   = split ? gm1 : gm0;
    float* gl   = split ? gl1 : gl0;

    const uint32_t smemu = (uint32_t)__cvta_generic_to_shared(fsm);
    const float* Kh0 = K + (size_t)head * SEQ * HDIM;
    const float* Vh0 = V + (size_t)head * SEQ * HDIM;

    auto prefetch = [&](int buf, int kb) {
        const uint32_t base = smemu + (SQF_W + buf * STAGE_W) * 4;
        const float* Kh = Kh0 + (size_t)kb * KT * HDIM;
        const float* Vh = Vh0 + (size_t)kb * KT * HDIM;
#pragma unroll
        for (int j = 0; j < 4; j++) {
            const int idx = tid + j * 128;
            const int r = idx >> 4, c4 = (idx & 15) << 2;
            cpa16(base + (r * FP + c4) * 4, Kh + r * HDIM + c4);
            cpa16(base + (KT * FP + r * VP + c4) * 4, Vh + r * HDIM + c4);
        }
    };

    const int half = 2 * (qblk + 1);
    const int t0 = split * half;
    const int t1 = t0 + half;

    prefetch(0, t0); cpa_commit();
    prefetch(1, t0 + 1); cpa_commit();

    // ---- repack Q into fragment-major smem (once) ----
    {
        const float* Qh = Q + ((size_t)head * SEQ + qblk * 128) * HDIM;
#pragma unroll
        for (int j = 0; j < 16; j++) {
            const int idx = tid + j * 128;
            const int r = idx >> 4, c4 = (idx & 15) << 2;
            float4 v = *(const float4*)(Qh + (size_t)r * HDIM + c4);
            const int widr = r >> 5, mh = (r >> 4) & 1, g4r = r & 7;
            const int rowH = (r >> 3) & 1;
            const int kk = c4 >> 3, colH = (c4 >> 2) & 1;
            const int s = rowH + 2 * colH;
            uint32_t* dst = sQf + (((widr * 8 + kk) * 2 + mh) * 8 + g4r) * 16 + s;
            dst[0]  = __float_as_uint(v.x);
            dst[4]  = __float_as_uint(v.y);
            dst[8]  = __float_as_uint(v.z);
            dst[12] = __float_as_uint(v.w);
        }
    }

    float o[2][8][4];
#pragma unroll
    for (int mh = 0; mh < 2; mh++)
#pragma unroll
        for (int nt = 0; nt < 8; nt++)
#pragma unroll
            for (int i = 0; i < 4; i++) o[mh][nt][i] = 0.f;

    float m[2][2], l[2][2];
#pragma unroll
    for (int mh = 0; mh < 2; mh++) {
        m[mh][0] = MINIT; m[mh][1] = MINIT;
        l[mh][0] = 0.f;   l[mh][1] = 0.f;
    }

    const int srcA = (lane & 28) | (t4 >> 1);
    const int srcB = srcA + 2;
    const bool odd = (t4 & 1);

    __syncthreads();

    const uint32_t* qbase = sQf + wid * 2048 + g4 * 16 + t4 * 4;

    for (int kb = t0; kb < t1; kb++) {
        if (kb + 1 < t1) cpa_wait<1>(); else cpa_wait<0>();
        __syncthreads();

        const uint32_t* sK = fsm + SQF_W + (kb & 1) * STAGE_W;
        const uint32_t* sV = sK + KT * FP;

        // ---- S = Q K^T ----
        float sc[2][4][4];
#pragma unroll
        for (int mh = 0; mh < 2; mh++)
#pragma unroll
            for (int nt = 0; nt < 4; nt++)
#pragma unroll
                for (int i = 0; i < 4; i++) sc[mh][nt][i] = 0.f;

        const uint32_t* kbase = sK + g4 * FP + t4;
#pragma unroll
        for (int kk = 0; kk < 8; kk++) {
            const uint4 qa0 = *(const uint4*)(qbase + kk * 256);
            const uint4 qa1 = *(const uint4*)(qbase + kk * 256 + 128);
#pragma unroll
            for (int nt = 0; nt < 4; nt++) {
                const uint32_t* bp = kbase + nt * 8 * FP + kk * 8;
                const uint32_t b0 = bp[0], b1 = bp[4];
                mma8(sc[0][nt], qa0.x, qa0.y, qa0.z, qa0.w, b0, b1);
                mma8(sc[1][nt], qa1.x, qa1.y, qa1.z, qa1.w, b0, b1);
            }
        }

        // ---- causal mask ----
        if (kb >= 4 * qblk) {
#pragma unroll
            for (int mh = 0; mh < 2; mh++) {
                const int r0 = qblk * 128 + wid * 32 + mh * 16 + g4;
                const int r1 = r0 + 8;
#pragma unroll
                for (int nt = 0; nt < 4; nt++) {
                    const int col = kb * KT + nt * 8 + (t4 << 1);
                    if (col > r0)     sc[mh][nt][0] = MMASK;
                    if (col + 1 > r0) sc[mh][nt][1] = MMASK;
                    if (col > r1)     sc[mh][nt][2] = MMASK;
                    if (col + 1 > r1) sc[mh][nt][3] = MMASK;
                }
            }
        }

        // ---- online softmax (log2 domain) ----
        float corr[2][2];
#pragma unroll
        for (int mh = 0; mh < 2; mh++) {
            float mx0 = MMASK, mx1 = MMASK;
#pragma unroll
            for (int nt = 0; nt < 4; nt++) {
                mx0 = fmaxf(mx0, fmaxf(sc[mh][nt][0], sc[mh][nt][1]));
                mx1 = fmaxf(mx1, fmaxf(sc[mh][nt][2], sc[mh][nt][3]));
            }
            mx0 = fmaxf(mx0, __shfl_xor_sync(0xffffffffu, mx0, 1));
            mx0 = fmaxf(mx0, __shfl_xor_sync(0xffffffffu, mx0, 2));
            mx1 = fmaxf(mx1, __shfl_xor_sync(0xffffffffu, mx1, 1));
            mx1 = fmaxf(mx1, __shfl_xor_sync(0xffffffffu, mx1, 2));

            const float mn0 = fmaxf(m[mh][0], mx0);
            const float mn1 = fmaxf(m[mh][1], mx1);
            corr[mh][0] = ex2(m[mh][0] - mn0);
            corr[mh][1] = ex2(m[mh][1] - mn1);
            m[mh][0] = mn0; m[mh][1] = mn1;

            float ls0 = 0.f, ls1 = 0.f;
#pragma unroll
            for (int nt = 0; nt < 4; nt++) {
                sc[mh][nt][0] = ex2(sc[mh][nt][0] - mn0);
                sc[mh][nt][1] = ex2(sc[mh][nt][1] - mn0);
                sc[mh][nt][2] = ex2(sc[mh][nt][2] - mn1);
                sc[mh][nt][3] = ex2(sc[mh][nt][3] - mn1);
                ls0 += sc[mh][nt][0] + sc[mh][nt][1];
                ls1 += sc[mh][nt][2] + sc[mh][nt][3];
            }
            ls0 += __shfl_xor_sync(0xffffffffu, ls0, 1);
            ls0 += __shfl_xor_sync(0xffffffffu, ls0, 2);
            ls1 += __shfl_xor_sync(0xffffffffu, ls1, 1);
            ls1 += __shfl_xor_sync(0xffffffffu, ls1, 2);
            l[mh][0] = l[mh][0] * corr[mh][0] + ls0;
            l[mh][1] = l[mh][1] * corr[mh][1] + ls1;

#pragma unroll
            for (int nt = 0; nt < 8; nt++) {
                o[mh][nt][0] *= corr[mh][0]; o[mh][nt][1] *= corr[mh][0];
                o[mh][nt][2] *= corr[mh][1]; o[mh][nt][3] *= corr[mh][1];
            }
        }

        // ---- O += P V : P fed as raw fp32 bits (RZ trunc, compensated) ----
        const uint32_t* vbase = sV + t4 * VP + g4;
#pragma unroll
        for (int kk = 0; kk < 4; kk++) {
            uint32_t pa[2][4];
#pragma unroll
            for (int mh = 0; mh < 2; mh++) {
                const float v0 = __shfl_sync(0xffffffffu, sc[mh][kk][0], srcA);
                const float v1 = __shfl_sync(0xffffffffu, sc[mh][kk][1], srcA);
                const float v2 = __shfl_sync(0xffffffffu, sc[mh][kk][2], srcA);
                const float v3 = __shfl_sync(0xffffffffu, sc[mh][kk][3], srcA);
                const float v4 = __shfl_sync(0xffffffffu, sc[mh][kk][0], srcB);
                const float v5 = __shfl_sync(0xffffffffu, sc[mh][kk][1], srcB);
                const float v6 = __shfl_sync(0xffffffffu, sc[mh][kk][2], srcB);
                const float v7 = __shfl_sync(0xffffffffu, sc[mh][kk][3], srcB);
                pa[mh][0] = __float_as_uint(odd ? v1 : v0);
                pa[mh][1] = __float_as_uint(odd ? v3 : v2);
                pa[mh][2] = __float_as_uint(odd ? v5 : v4);
                pa[mh][3] = __float_as_uint(odd ? v7 : v6);
            }
            const uint32_t* vrow = vbase + kk * 8 * VP;
#pragma unroll
            for (int nt = 0; nt < 8; nt++) {
                const uint32_t b0 = vrow[nt * 8];
                const uint32_t b1 = vrow[4 * VP + nt * 8];
                mma8(o[0][nt], pa[0][0], pa[0][1], pa[0][2], pa[0][3], b0, b1);
                mma8(o[1][nt], pa[1][0], pa[1][1], pa[1][2], pa[1][3], b0, b1);
            }
        }

        __syncthreads();
        if (kb + 2 < t1) { prefetch(kb & 1, kb + 2); cpa_commit(); }
    }

    // ---- write own raw partial + (m, l) ----
#pragma unroll
    for (int mh = 0; mh < 2; mh++) {
        const int r0 = qblk * 128 + wid * 32 + mh * 16 + g4;
#pragma unroll
        for (int nt = 0; nt < 8; nt++) {
            const int col = head * HDIM + nt * 8 + (t4 << 1);
            *(float2*)(part + (size_t)r0 * DIM + col) =
                make_float2(o[mh][nt][0], o[mh][nt][1]);
            *(float2*)(part + (size_t)(r0 + 8) * DIM + col) =
                make_float2(o[mh][nt][2], o[mh][nt][3]);
        }
        if (t4 == 0) {
            gm[head * SEQ + r0]     = m[mh][0];
            gl[head * SEQ + r0]     = l[mh][0];
            gm[head * SEQ + r0 + 8] = m[mh][1];
            gl[head * SEQ + r0 + 8] = l[mh][1];
        }
    }

    // ---- last-CTA-done merge ----
    __threadfence();
    __syncthreads();
    if (tid == 0) {
        const int old = atomicAdd(&g_cnt[head * (SEQ / 128) + qblk], 1);
        ((volatile int*)fsm)[0] = old;
    }
    __syncthreads();
    const int old = ((volatile int*)fsm)[0];
    if (old != 1) return;                 // first finisher exits
    __threadfence();                      // acquire other's writes
    if (tid == 0) g_cnt[head * (SEQ / 128) + qblk] = 0;   // replay-safe reset

    const float* po  = split ? p0 : p1;   // other's partial
    const float* gmo = split ? gm0 : gm1;
    const float* glo = split ? gl0 : gl1;

#pragma unroll
    for (int mh = 0; mh < 2; mh++) {
        const int r0 = qblk * 128 + wid * 32 + mh * 16 + g4;
#pragma unroll
        for (int rh = 0; rh < 2; rh++) {
            const int row = r0 + rh * 8;
            const float mOwn = m[mh][rh], lOwn = l[mh][rh];
            const float mOth = gmo[head * SEQ + row];
            const float lOth = glo[head * SEQ + row];
            // fixed (split0, split1) orientation for determinism
            const float mA = split ? mOth : mOwn;
            const float lA = split ? lOth : lOwn;
            const float mB = split ? mOwn : mOth;
            const float lB = split ? lOwn : lOth;
            const float ms = fmaxf(mA, mB);
            const float wA = ex2(mA - ms), wB = ex2(mB - ms);
            const float inv = PCOMP / (lA * wA + lB * wB);
            const float wOwn = split ? wB : wA;
            const float wOth = split ? wA : wB;
#pragma unroll
            for (int nt = 0; nt < 8; nt++) {
                const int col = head * HDIM + nt * 8 + (t4 << 1);
                const float2 ov = *(const float2*)(po + (size_t)row * DIM + col);
                const float x0 = (o[mh][nt][rh * 2 + 0] * wOwn + ov.x * wOth) * inv;
                const float x1 = (o[mh][nt][rh * 2 + 1] * wOwn + ov.y * wOth) * inv;
                *(float2*)(att + (size_t)row * DIM + col) = make_float2(
                    __uint_as_float(f2t(x0)), __uint_as_float(f2t(x1)));
            }
        }
    }
}

// ---------------------------------------------------------------------------
// Launch
// ---------------------------------------------------------------------------
extern "C" void kernel_launch(void* const* d_in, const int* in_sizes, int n_in,
                              void* d_out, int out_size)
{
    const float* x    = (const float*)d_in[0];
    const float* cosT = (const float*)d_in[1];
    const float* sinT = (const float*)d_in[2];
    const float* wq   = (const float*)d_in[4];
    const float* wk   = (const float*)d_in[5];
    const float* wv   = (const float*)d_in[6];
    const float* wo   = (const float*)d_in[7];
    float* out = (float*)d_out;

    float *qp, *kp, *vp, *ap, *xt, *wqt, *wkt, *wvt, *wot;
    float *p0, *p1, *m0, *l0, *m1, *l1;
    cudaGetSymbolAddress((void**)&qp, g_q);
    cudaGetSymbolAddress((void**)&kp, g_k);
    cudaGetSymbolAddress((void**)&vp, g_v);
    cudaGetSymbolAddress((void**)&ap, g_att);
    cudaGetSymbolAddress((void**)&xt, g_xt);
    cudaGetSymbolAddress((void**)&wqt, g_wq);
    cudaGetSymbolAddress((void**)&wkt, g_wk);
    cudaGetSymbolAddress((void**)&wvt, g_wv);
    cudaGetSymbolAddress((void**)&wot, g_wo);
    cudaGetSymbolAddress((void**)&p0, g_p0);
    cudaGetSymbolAddress((void**)&p1, g_p1);
    cudaGetSymbolAddress((void**)&m0, g_m0);
    cudaGetSymbolAddress((void**)&l0, g_l0);
    cudaGetSymbolAddress((void**)&m1, g_m1);
    cudaGetSymbolAddress((void**)&l1, g_l1);

    cudaFuncSetAttribute(flash_split,
                         cudaFuncAttributeMaxDynamicSharedMemorySize, FLASH_SMEM);
    cudaFuncSetAttribute(gemm_tf32,
                         cudaFuncAttributeMaxDynamicSharedMemorySize, GSMEM);

    // Convert inputs to tf32 bits once
    cvt_tf32<<<512, 256>>>(x, xt, SEQ * DIM / 4);
    dim3 wgrid(128, 1, 4);
    cvt_tf32_w<<<wgrid, 256>>>(wq, wqt, wk, wkt, wv, wvt, wo, wot, DIM * DIM / 4);

    // Fused QKV projections
    dim3 ggrid(DIM / 128, SEQ / 128, 3);
    gemm_tf32<<<ggrid, 128, GSMEM>>>(xt, wqt, wkt, wvt, qp, kp, vp, cosT, sinT, 1);

    // Split-K flash with in-kernel merge
    dim3 fgrid(2 * (SEQ / 128), NH);
    flash_split<<<fgrid, 128, FLASH_SMEM>>>(qp, kp, vp, p0, p1, m0, l0, m1, l1, ap);

    // Output projection
    dim3 ogrid(DIM / 128, SEQ / 128, 1);
    gemm_tf32<<<ogrid, 128, GSMEM>>>(ap, wot, wot, wot, out, out, out, cosT, sinT, 0);
}

// round 14
// speedup vs baseline: 1.2826x; 1.1990x over previous
#include <cuda_runtime.h>
#include <cuda_fp16.h>
#include <math.h>
#include <stdint.h>

#define SEQ 4096
#define DIM 1024
#define NH  16
#define HDIM 64

// Scratch
__device__ float  g_q[NH * SEQ * HDIM];   // [h][s][hd] tf32 bits, pre-scaled
__device__ float  g_k[NH * SEQ * HDIM];   // [h][s][hd] tf32 bits
__device__ float  g_v[NH * SEQ * HDIM];   // [h][s][hd] tf32 bits
__device__ __half g_att[SEQ * DIM];       // [s][d] half (merged attention out)
__device__ __half g_xh[SEQ * DIM];        // x as half
__device__ __half g_wqh[DIM * DIM];       // weights as half
__device__ __half g_wkh[DIM * DIM];
__device__ __half g_wvh[DIM * DIM];
__device__ __half g_woh[DIM * DIM];
// split-K partials (raw fp32)
__device__ float g_p0[SEQ * DIM];
__device__ float g_p1[SEQ * DIM];
__device__ float g_m0[NH * SEQ];
__device__ float g_l0[NH * SEQ];
__device__ float g_m1[NH * SEQ];
__device__ float g_l1[NH * SEQ];
// merge counters (zero-init; merger resets -> replay-safe)
__device__ int g_cnt[NH * (SEQ / 128)];

#define QSCALE (0.125f * 1.4426950408889634f)   // 1/sqrt(64) * log2(e)
#define MINIT  (-1.6e38f)
#define MMASK  (-3.2e38f)
#define PCOMP  (1.000244140625f)                // 1 + 2^-12 (RZ-trunc bias comp)

__device__ __forceinline__ uint32_t f2t(float f) {
    uint32_t u;
    asm("cvt.rna.tf32.f32 %0, %1;" : "=r"(u) : "f"(f));
    return u;
}

__device__ __forceinline__ float ex2(float x) {
    float r;
    asm("ex2.approx.f32 %0, %1;" : "=f"(r) : "f"(x));
    return r;
}

// tf32 m16n8k8 (flash)
__device__ __forceinline__ void mma8(float c[4],
    uint32_t a0, uint32_t a1, uint32_t a2, uint32_t a3,
    uint32_t b0, uint32_t b1)
{
    asm volatile(
        "mma.sync.aligned.m16n8k8.row.col.f32.tf32.tf32.f32 "
        "{%0,%1,%2,%3},{%4,%5,%6,%7},{%8,%9},{%0,%1,%2,%3};"
        : "+f"(c[0]), "+f"(c[1]), "+f"(c[2]), "+f"(c[3])
        : "r"(a0), "r"(a1), "r"(a2), "r"(a3), "r"(b0), "r"(b1));
}

// f16 m16n8k16, f32 accumulate (GEMMs)
__device__ __forceinline__ void mma16h(float c[4],
    uint32_t a0, uint32_t a1, uint32_t a2, uint32_t a3,
    uint32_t b0, uint32_t b1)
{
    asm volatile(
        "mma.sync.aligned.m16n8k16.row.col.f32.f16.f16.f32 "
        "{%0,%1,%2,%3},{%4,%5,%6,%7},{%8,%9},{%0,%1,%2,%3};"
        : "+f"(c[0]), "+f"(c[1]), "+f"(c[2]), "+f"(c[3])
        : "r"(a0), "r"(a1), "r"(a2), "r"(a3), "r"(b0), "r"(b1));
}

__device__ __forceinline__ void cpa16(uint32_t dst_smem, const void* src) {
    asm volatile("cp.async.cg.shared.global [%0], [%1], 16;"
                 :: "r"(dst_smem), "l"(src));
}
__device__ __forceinline__ void cpa_commit() {
    asm volatile("cp.async.commit_group;");
}
template<int N>
__device__ __forceinline__ void cpa_wait() {
    asm volatile("cp.async.wait_group %0;" :: "n"(N));
}

// ---------------------------------------------------------------------------
// Convert fp32 -> fp16
// ---------------------------------------------------------------------------
__global__ void cvt_h(const float* __restrict__ src, __half* __restrict__ dst,
                      int n4)
{
    for (int i = blockIdx.x * blockDim.x + threadIdx.x; i < n4;
         i += gridDim.x * blockDim.x) {
        float4 v = ((const float4*)src)[i];
        __half2 h0 = __floats2half2_rn(v.x, v.y);
        __half2 h1 = __floats2half2_rn(v.z, v.w);
        ((uint2*)dst)[i] = make_uint2(*(uint32_t*)&h0, *(uint32_t*)&h1);
    }
}

__global__ void cvt_h_w(const float* __restrict__ s0, __half* __restrict__ d0,
                        const float* __restrict__ s1, __half* __restrict__ d1,
                        const float* __restrict__ s2, __half* __restrict__ d2,
                        const float* __restrict__ s3, __half* __restrict__ d3,
                        int n4)
{
    const float* src; __half* dst;
    if (blockIdx.z == 0)      { src = s0; dst = d0; }
    else if (blockIdx.z == 1) { src = s1; dst = d1; }
    else if (blockIdx.z == 2) { src = s2; dst = d2; }
    else                      { src = s3; dst = d3; }
    for (int i = blockIdx.x * blockDim.x + threadIdx.x; i < n4;
         i += gridDim.x * blockDim.x) {
        float4 v = ((const float4*)src)[i];
        __half2 h0 = __floats2half2_rn(v.x, v.y);
        __half2 h1 = __floats2half2_rn(v.z, v.w);
        ((uint2*)dst)[i] = make_uint2(*(uint32_t*)&h0, *(uint32_t*)&h1);
    }
}

// ---------------------------------------------------------------------------
// FP16 GEMM (mma.sync m16n8k16, f32 acc), 64x64 warp tiles, 128 threads,
// BK=32 (halves), 3-stage cp.async, ONE barrier per chunk.
// C[4096,1024] = A[M,K] * W[N,K]^T, A/W half.
// mode 0: plain f32 out; 1: RoPE+QSCALE -> tf32 [h][s][hd];
// 2: RoPE -> tf32 [h][s][hd]; 3: tf32 [h][s][hd]
// smem rows stored as uint32 (half2), stride 20 (16 data + 4 pad).
// ---------------------------------------------------------------------------
#define GBK   32
#define GSA   20
#define GSTW  (128 * GSA)                 // uints per operand per stage
#define GSTB  (2 * GSTW * 4)              // stage bytes (A + B) = 20480
#define GSMEM (3 * GSTB)                  // 61440

__global__ void __launch_bounds__(128) gemm_h(
    const __half* __restrict__ A,
    const __half* __restrict__ W0, const __half* __restrict__ W1,
    const __half* __restrict__ W2,
    float* __restrict__ out0, float* __restrict__ out1,
    float* __restrict__ out2,
    const float* __restrict__ cosT, const float* __restrict__ sinT,
    int mode0)
{
    extern __shared__ uint32_t gsm[];

    const __half* W; float* out; int mode;
    if (blockIdx.z == 0)      { W = W0; out = out0; mode = mode0; }
    else if (blockIdx.z == 1) { W = W1; out = out1; mode = 2; }
    else                      { W = W2; out = out2; mode = 3; }

    const int tid  = threadIdx.x;
    const int lane = tid & 31;
    const int wid  = tid >> 5;
    const int wm   = wid >> 1;
    const int wn   = wid & 1;
    const int g4   = lane >> 2;
    const int t4   = lane & 3;

    const int mBase = blockIdx.y * 128;
    const int nBase = blockIdx.x * 128;

    const uint32_t smemu = (uint32_t)__cvta_generic_to_shared(gsm);

    // prefetch one 32-half K chunk of A and W into stage s
    // A chunk = 128 rows x 64B = 512 x 16B; 128 threads x 4
    auto prefetch = [&](int s, int t) {
        const int koff = t * GBK;
        const uint32_t abase = smemu + s * GSTB;
        const uint32_t bbase = abase + GSTW * 4;
#pragma unroll
        for (int j = 0; j < 4; j++) {
            const int idx = tid + j * 128;       // 0..511
            const int r = idx >> 2, c16 = idx & 3;
            cpa16(abase + (r * GSA + c16 * 4) * 4,
                  A + (size_t)(mBase + r) * DIM + koff + c16 * 8);
            cpa16(bbase + (r * GSA + c16 * 4) * 4,
                  W + (size_t)(nBase + r) * DIM + koff + c16 * 8);
        }
    };

    float c[4][8][4];
#pragma unroll
    for (int mt = 0; mt < 4; mt++)
#pragma unroll
        for (int nt = 0; nt < 8; nt++)
#pragma unroll
            for (int i = 0; i < 4; i++) c[mt][nt][i] = 0.f;

    const int NT = DIM / GBK;   // 32 chunks
    prefetch(0, 0); cpa_commit();
    prefetch(1, 1); cpa_commit();

    for (int t = 0; t < NT; t++) {
        if (t + 1 < NT) cpa_wait<1>(); else cpa_wait<0>();
        __syncthreads();

        if (t + 2 < NT) { prefetch((t + 2) % 3, t + 2); cpa_commit(); }

        const uint32_t* a_s = gsm + (t % 3) * (GSTB / 4);
        const uint32_t* b_s = a_s + GSTW;
#pragma unroll
        for (int ks = 0; ks < 2; ks++) {       // k=16 per step
            const int j = ks * 8 + t4;
            uint32_t af[4][4], bf[8][2];
#pragma unroll
            for (int mt = 0; mt < 4; mt++) {
                const int r = wm * 64 + mt * 16 + g4;
                af[mt][0] = a_s[r * GSA + j];
                af[mt][1] = a_s[(r + 8) * GSA + j];
                af[mt][2] = a_s[r * GSA + j + 4];
                af[mt][3] = a_s[(r + 8) * GSA + j + 4];
            }
#pragma unroll
            for (int nt = 0; nt < 8; nt++) {
                const int r = wn * 64 + nt * 8 + g4;
                bf[nt][0] = b_s[r * GSA + j];
                bf[nt][1] = b_s[r * GSA + j + 4];
            }
#pragma unroll
            for (int mt = 0; mt < 4; mt++)
#pragma unroll
                for (int nt = 0; nt < 8; nt++)
                    mma16h(c[mt][nt], af[mt][0], af[mt][1], af[mt][2], af[mt][3],
                           bf[nt][0], bf[nt][1]);
        }
    }

    // Epilogue (C fragment layout identical to tf32 k8 version)
#pragma unroll
    for (int mt = 0; mt < 4; mt++) {
        const int r0 = mBase + wm * 64 + mt * 16 + g4;
#pragma unroll
        for (int nt = 0; nt < 8; nt++) {
            const int colg = nBase + wn * 64 + nt * 8 + (t4 << 1);
            const float* cc = c[mt][nt];
            if (mode == 0) {
                *(float2*)(out + (size_t)r0 * DIM + colg)       = make_float2(cc[0], cc[1]);
                *(float2*)(out + (size_t)(r0 + 8) * DIM + colg) = make_float2(cc[2], cc[3]);
                continue;
            }
            const int head = colg >> 6;
            const int hd   = colg & 63;
            const int f    = hd >> 1;
#pragma unroll
            for (int h = 0; h < 2; h++) {
                const int row = r0 + h * 8;
                float e = cc[h * 2 + 0], o = cc[h * 2 + 1];
                float re = e, ro = o;
                if (mode != 3) {
                    const float cth = cosT[row * 32 + f];
                    const float sth = sinT[row * 32 + f];
                    re = e * cth - o * sth;
                    ro = e * sth + o * cth;
                    if (mode == 1) { re *= QSCALE; ro *= QSCALE; }
                }
                float* dst = out + ((size_t)head * SEQ + row) * HDIM + hd;
                dst[0] = __uint_as_float(f2t(re));
                dst[1] = __uint_as_float(f2t(ro));
            }
        }
    }
}

// ---------------------------------------------------------------------------
// Split-K TF32 flash attention with in-kernel merge (unchanged from R13,
// except merged output is written as half into g_att).
// ---------------------------------------------------------------------------
#define FP  68
#define VP  72
#define KT  32
#define SQF_W  8192
#define STAGE_W (KT * FP + KT * VP)
#define FLASH_SMEM ((SQF_W + 2 * STAGE_W) * (int)sizeof(uint32_t))

__global__ void __launch_bounds__(128, 3) flash_split(
    const float* __restrict__ Q, const float* __restrict__ K,
    const float* __restrict__ V,
    float* __restrict__ p0, float* __restrict__ p1,
    float* __restrict__ gm0, float* __restrict__ gl0,
    float* __restrict__ gm1, float* __restrict__ gl1,
    __half* __restrict__ att)
{
    extern __shared__ uint32_t fsm[];
    uint32_t* sQf = fsm;

    const int tid  = threadIdx.x;
    const int lane = tid & 31;
    const int wid  = tid >> 5;
    const int g4   = lane >> 2;
    const int t4   = lane & 3;

    const int enc  = gridDim.x - 1 - blockIdx.x;
    const int qblk = enc >> 1;
    const int split = enc & 1;
    const int head = blockIdx.y;

    float* part = split ? p1 : p0;
    float* gm   = split ? gm1 : gm0;
    float* gl   = split ? gl1 : gl0;

    const uint32_t smemu = (uint32_t)__cvta_generic_to_shared(fsm);
    const float* Kh0 = K + (size_t)head * SEQ * HDIM;
    const float* Vh0 = V + (size_t)head * SEQ * HDIM;

    auto prefetch = [&](int buf, int kb) {
        const uint32_t base = smemu + (SQF_W + buf * STAGE_W) * 4;
        const float* Kh = Kh0 + (size_t)kb * KT * HDIM;
        const float* Vh = Vh0 + (size_t)kb * KT * HDIM;
#pragma unroll
        for (int j = 0; j < 4; j++) {
            const int idx = tid + j * 128;
            const int r = idx >> 4, c4 = (idx & 15) << 2;
            cpa16(base + (r * FP + c4) * 4, Kh + r * HDIM + c4);
            cpa16(base + (KT * FP + r * VP + c4) * 4, Vh + r * HDIM + c4);
        }
    };

    const int half = 2 * (qblk + 1);
    const int t0 = split * half;
    const int t1 = t0 + half;

    prefetch(0, t0); cpa_commit();
    prefetch(1, t0 + 1); cpa_commit();

    // repack Q into fragment-major smem (once)
    {
        const float* Qh = Q + ((size_t)head * SEQ + qblk * 128) * HDIM;
#pragma unroll
        for (int j = 0; j < 16; j++) {
            const int idx = tid + j * 128;
            const int r = idx >> 4, c4 = (idx & 15) << 2;
            float4 v = *(const float4*)(Qh + (size_t)r * HDIM + c4);
            const int widr = r >> 5, mh = (r >> 4) & 1, g4r = r & 7;
            const int rowH = (r >> 3) & 1;
            const int kk = c4 >> 3, colH = (c4 >> 2) & 1;
            const int s = rowH + 2 * colH;
            uint32_t* dst = sQf + (((widr * 8 + kk) * 2 + mh) * 8 + g4r) * 16 + s;
            dst[0]  = __float_as_uint(v.x);
            dst[4]  = __float_as_uint(v.y);
            dst[8]  = __float_as_uint(v.z);
            dst[12] = __float_as_uint(v.w);
        }
    }

    float o[2][8][4];
#pragma unroll
    for (int mh = 0; mh < 2; mh++)
#pragma unroll
        for (int nt = 0; nt < 8; nt++)
#pragma unroll
            for (int i = 0; i < 4; i++) o[mh][nt][i] = 0.f;

    float m[2][2], l[2][2];
#pragma unroll
    for (int mh = 0; mh < 2; mh++) {
        m[mh][0] = MINIT; m[mh][1] = MINIT;
        l[mh][0] = 0.f;   l[mh][1] = 0.f;
    }

    const int srcA = (lane & 28) | (t4 >> 1);
    const int srcB = srcA + 2;
    const bool odd = (t4 & 1);

    __syncthreads();

    const uint32_t* qbase = sQf + wid * 2048 + g4 * 16 + t4 * 4;

    for (int kb = t0; kb < t1; kb++) {
        if (kb + 1 < t1) cpa_wait<1>(); else cpa_wait<0>();
        __syncthreads();

        const uint32_t* sK = fsm + SQF_W + (kb & 1) * STAGE_W;
        const uint32_t* sV = sK + KT * FP;

        float sc[2][4][4];
#pragma unroll
        for (int mh = 0; mh < 2; mh++)
#pragma unroll
            for (int nt = 0; nt < 4; nt++)
#pragma unroll
                for (int i = 0; i < 4; i++) sc[mh][nt][i] = 0.f;

        const uint32_t* kbase = sK + g4 * FP + t4;
#pragma unroll
        for (int kk = 0; kk < 8; kk++) {
            const uint4 qa0 = *(const uint4*)(qbase + kk * 256);
            const uint4 qa1 = *(const uint4*)(qbase + kk * 256 + 128);
#pragma unroll
            for (int nt = 0; nt < 4; nt++) {
                const uint32_t* bp = kbase + nt * 8 * FP + kk * 8;
                const uint32_t b0 = bp[0], b1 = bp[4];
                mma8(sc[0][nt], qa0.x, qa0.y, qa0.z, qa0.w, b0, b1);
                mma8(sc[1][nt], qa1.x, qa1.y, qa1.z, qa1.w, b0, b1);
            }
        }

        if (kb >= 4 * qblk) {
#pragma unroll
            for (int mh = 0; mh < 2; mh++) {
                const int r0 = qblk * 128 + wid * 32 + mh * 16 + g4;
                const int r1 = r0 + 8;
#pragma unroll
                for (int nt = 0; nt < 4; nt++) {
                    const int col = kb * KT + nt * 8 + (t4 << 1);
                    if (col > r0)     sc[mh][nt][0] = MMASK;
                    if (col + 1 > r0) sc[mh][nt][1] = MMASK;
                    if (col > r1)     sc[mh][nt][2] = MMASK;
                    if (col + 1 > r1) sc[mh][nt][3] = MMASK;
                }
            }
        }

        float corr[2][2];
#pragma unroll
        for (int mh = 0; mh < 2; mh++) {
            float mx0 = MMASK, mx1 = MMASK;
#pragma unroll
            for (int nt = 0; nt < 4; nt++) {
                mx0 = fmaxf(mx0, fmaxf(sc[mh][nt][0], sc[mh][nt][1]));
                mx1 = fmaxf(mx1, fmaxf(sc[mh][nt][2], sc[mh][nt][3]));
            }
            mx0 = fmaxf(mx0, __shfl_xor_sync(0xffffffffu, mx0, 1));
            mx0 = fmaxf(mx0, __shfl_xor_sync(0xffffffffu, mx0, 2));
            mx1 = fmaxf(mx1, __shfl_xor_sync(0xffffffffu, mx1, 1));
            mx1 = fmaxf(mx1, __shfl_xor_sync(0xffffffffu, mx1, 2));

            const float mn0 = fmaxf(m[mh][0], mx0);
            const float mn1 = fmaxf(m[mh][1], mx1);
            corr[mh][0] = ex2(m[mh][0] - mn0);
            corr[mh][1] = ex2(m[mh][1] - mn1);
            m[mh][0] = mn0; m[mh][1] = mn1;

            float ls0 = 0.f, ls1 = 0.f;
#pragma unroll
            for (int nt = 0; nt < 4; nt++) {
                sc[mh][nt][0] = ex2(sc[mh][nt][0] - mn0);
                sc[mh][nt][1] = ex2(sc[mh][nt][1] - mn0);
                sc[mh][nt][2] = ex2(sc[mh][nt][2] - mn1);
                sc[mh][nt][3] = ex2(sc[mh][nt][3] - mn1);
                ls0 += sc[mh][nt][0] + sc[mh][nt][1];
                ls1 += sc[mh][nt][2] + sc[mh][nt][3];
            }
            ls0 += __shfl_xor_sync(0xffffffffu, ls0, 1);
            ls0 += __shfl_xor_sync(0xffffffffu, ls0, 2);
            ls1 += __shfl_xor_sync(0xffffffffu, ls1, 1);
            ls1 += __shfl_xor_sync(0xffffffffu, ls1, 2);
            l[mh][0] = l[mh][0] * corr[mh][0] + ls0;
            l[mh][1] = l[mh][1] * corr[mh][1] + ls1;

#pragma unroll
            for (int nt = 0; nt < 8; nt++) {
                o[mh][nt][0] *= corr[mh][0]; o[mh][nt][1] *= corr[mh][0];
                o[mh][nt][2] *= corr[mh][1]; o[mh][nt][3] *= corr[mh][1];
            }
        }

        const uint32_t* vbase = sV + t4 * VP + g4;
#pragma unroll
        for (int kk = 0; kk < 4; kk++) {
            uint32_t pa[2][4];
#pragma unroll
            for (int mh = 0; mh < 2; mh++) {
                const float v0 = __shfl_sync(0xffffffffu, sc[mh][kk][0], srcA);
                const float v1 = __shfl_sync(0xffffffffu, sc[mh][kk][1], srcA);
                const float v2 = __shfl_sync(0xffffffffu, sc[mh][kk][2], srcA);
                const float v3 = __shfl_sync(0xffffffffu, sc[mh][kk][3], srcA);
                const float v4 = __shfl_sync(0xffffffffu, sc[mh][kk][0], srcB);
                const float v5 = __shfl_sync(0xffffffffu, sc[mh][kk][1], srcB);
                const float v6 = __shfl_sync(0xffffffffu, sc[mh][kk][2], srcB);
                const float v7 = __shfl_sync(0xffffffffu, sc[mh][kk][3], srcB);
                pa[mh][0] = __float_as_uint(odd ? v1 : v0);
                pa[mh][1] = __float_as_uint(odd ? v3 : v2);
                pa[mh][2] = __float_as_uint(odd ? v5 : v4);
                pa[mh][3] = __float_as_uint(odd ? v7 : v6);
            }
            const uint32_t* vrow = vbase + kk * 8 * VP;
#pragma unroll
            for (int nt = 0; nt < 8; nt++) {
                const uint32_t b0 = vrow[nt * 8];
                const uint32_t b1 = vrow[4 * VP + nt * 8];
                mma8(o[0][nt], pa[0][0], pa[0][1], pa[0][2], pa[0][3], b0, b1);
                mma8(o[1][nt], pa[1][0], pa[1][1], pa[1][2], pa[1][3], b0, b1);
            }
        }

        __syncthreads();
        if (kb + 2 < t1) { prefetch(kb & 1, kb + 2); cpa_commit(); }
    }

    // write own raw partial + (m, l)
#pragma unroll
    for (int mh = 0; mh < 2; mh++) {
        const int r0 = qblk * 128 + wid * 32 + mh * 16 + g4;
#pragma unroll
        for (int nt = 0; nt < 8; nt++) {
            const int col = head * HDIM + nt * 8 + (t4 << 1);
            *(float2*)(part + (size_t)r0 * DIM + col) =
                make_float2(o[mh][nt][0], o[mh][nt][1]);
            *(float2*)(part + (size_t)(r0 + 8) * DIM + col) =
                make_float2(o[mh][nt][2], o[mh][nt][3]);
        }
        if (t4 == 0) {
            gm[head * SEQ + r0]     = m[mh][0];
            gl[head * SEQ + r0]     = l[mh][0];
            gm[head * SEQ + r0 + 8] = m[mh][1];
            gl[head * SEQ + r0 + 8] = l[mh][1];
        }
    }

    // last-CTA-done merge
    __threadfence();
    __syncthreads();
    if (tid == 0) {
        const int old = atomicAdd(&g_cnt[head * (SEQ / 128) + qblk], 1);
        ((volatile int*)fsm)[0] = old;
    }
    __syncthreads();
    const int old = ((volatile int*)fsm)[0];
    if (old != 1) return;
    __threadfence();
    if (tid == 0) g_cnt[head * (SEQ / 128) + qblk] = 0;

    const float* po  = split ? p0 : p1;
    const float* gmo = split ? gm0 : gm1;
    const float* glo = split ? gl0 : gl1;

#pragma unroll
    for (int mh = 0; mh < 2; mh++) {
        const int r0 = qblk * 128 + wid * 32 + mh * 16 + g4;
#pragma unroll
        for (int rh = 0; rh < 2; rh++) {
            const int row = r0 + rh * 8;
            const float mOwn = m[mh][rh], lOwn = l[mh][rh];
            const float mOth = gmo[head * SEQ + row];
            const float lOth = glo[head * SEQ + row];
            const float mA = split ? mOth : mOwn;
            const float lA = split ? lOth : lOwn;
            const float mB = split ? mOwn : mOth;
            const float lB = split ? lOwn : lOth;
            const float ms = fmaxf(mA, mB);
            const float wA = ex2(mA - ms), wB = ex2(mB - ms);
            const float inv = PCOMP / (lA * wA + lB * wB);
            const float wOwn = split ? wB : wA;
            const float wOth = split ? wA : wB;
#pragma unroll
            for (int nt = 0; nt < 8; nt++) {
                const int col = head * HDIM + nt * 8 + (t4 << 1);
                const float2 ov = *(const float2*)(po + (size_t)row * DIM + col);
                const float x0 = (o[mh][nt][rh * 2 + 0] * wOwn + ov.x * wOth) * inv;
                const float x1 = (o[mh][nt][rh * 2 + 1] * wOwn + ov.y * wOth) * inv;
                __half2 hv = __floats2half2_rn(x0, x1);
                *(__half2*)(att + (size_t)row * DIM + col) = hv;
            }
        }
    }
}

// ---------------------------------------------------------------------------
// Launch
// ---------------------------------------------------------------------------
extern "C" void kernel_launch(void* const* d_in, const int* in_sizes, int n_in,
                              void* d_out, int out_size)
{
    const float* x    = (const float*)d_in[0];
    const float* cosT = (const float*)d_in[1];
    const float* sinT = (const float*)d_in[2];
    const float* wq   = (const float*)d_in[4];
    const float* wk   = (const float*)d_in[5];
    const float* wv   = (const float*)d_in[6];
    const float* wo   = (const float*)d_in[7];
    float* out = (float*)d_out;

    float *qp, *kp, *vp, *p0, *p1, *m0, *l0, *m1, *l1;
    __half *ap, *xh, *wqh, *wkh, *wvh, *woh;
    cudaGetSymbolAddress((void**)&qp, g_q);
    cudaGetSymbolAddress((void**)&kp, g_k);
    cudaGetSymbolAddress((void**)&vp, g_v);
    cudaGetSymbolAddress((void**)&ap, g_att);
    cudaGetSymbolAddress((void**)&xh, g_xh);
    cudaGetSymbolAddress((void**)&wqh, g_wqh);
    cudaGetSymbolAddress((void**)&wkh, g_wkh);
    cudaGetSymbolAddress((void**)&wvh, g_wvh);
    cudaGetSymbolAddress((void**)&woh, g_woh);
    cudaGetSymbolAddress((void**)&p0, g_p0);
    cudaGetSymbolAddress((void**)&p1, g_p1);
    cudaGetSymbolAddress((void**)&m0, g_m0);
    cudaGetSymbolAddress((void**)&l0, g_l0);
    cudaGetSymbolAddress((void**)&m1, g_m1);
    cudaGetSymbolAddress((void**)&l1, g_l1);

    cudaFuncSetAttribute(flash_split,
                         cudaFuncAttributeMaxDynamicSharedMemorySize, FLASH_SMEM);
    cudaFuncSetAttribute(gemm_h,
                         cudaFuncAttributeMaxDynamicSharedMemorySize, GSMEM);

    // Convert inputs to fp16 once
    cvt_h<<<512, 256>>>(x, xh, SEQ * DIM / 4);
    dim3 wgrid(128, 1, 4);
    cvt_h_w<<<wgrid, 256>>>(wq, wqh, wk, wkh, wv, wvh, wo, woh, DIM * DIM / 4);

    // Fused QKV projections (fp16 MMA; outputs tf32 bits for flash)
    dim3 ggrid(DIM / 128, SEQ / 128, 3);
    gemm_h<<<ggrid, 128, GSMEM>>>(xh, wqh, wkh, wvh, qp, kp, vp, cosT, sinT, 1);

    // Split-K flash with in-kernel merge (tf32; writes half att)
    dim3 fgrid(2 * (SEQ / 128), NH);
    flash_split<<<fgrid, 128, FLASH_SMEM>>>(qp, kp, vp, p0, p1, m0, l0, m1, l1, ap);

    // Output projection (fp16 MMA, fp32 out)
    dim3 ogrid(DIM / 128, SEQ / 128, 1);
    gemm_h<<<ogrid, 128, GSMEM>>>(ap, woh, woh, woh, out, out, out, cosT, sinT, 0);
}

// round 15
// speedup vs baseline: 1.7212x; 1.3419x over previous
#include <cuda_runtime.h>
#include <cuda_fp16.h>
#include <math.h>
#include <stdint.h>

#define SEQ 4096
#define DIM 1024
#define NH  16
#define HDIM 64

// Scratch
__device__ __half g_qh[NH * SEQ * HDIM];  // [h][s][hd] half, pre-scaled
__device__ __half g_kh[NH * SEQ * HDIM];  // [h][s][hd] half
__device__ __half g_vt[NH * SEQ * HDIM];  // [h][tile32][d64][key32] half (transposed)
__device__ __half g_att[SEQ * DIM];       // [s][d] half (merged attention out)
__device__ __half g_xh[SEQ * DIM];        // x as half
__device__ __half g_wqh[DIM * DIM];       // weights as half
__device__ __half g_wkh[DIM * DIM];
__device__ __half g_wvh[DIM * DIM];
__device__ __half g_woh[DIM * DIM];
// split-K partials (raw fp32)
__device__ float g_p0[SEQ * DIM];
__device__ float g_p1[SEQ * DIM];
__device__ float g_m0[NH * SEQ];
__device__ float g_l0[NH * SEQ];
__device__ float g_m1[NH * SEQ];
__device__ float g_l1[NH * SEQ];
// merge counters (zero-init; merger resets -> replay-safe)
__device__ int g_cnt[NH * (SEQ / 128)];

#define QSCALE (0.125f * 1.4426950408889634f)   // 1/sqrt(64) * log2(e)
#define MINIT  (-1.6e38f)
#define MMASK  (-3.2e38f)

__device__ __forceinline__ float ex2(float x) {
    float r;
    asm("ex2.approx.f32 %0, %1;" : "=f"(r) : "f"(x));
    return r;
}

// f16 m16n8k16, f32 accumulate
__device__ __forceinline__ void mma16h(float c[4],
    uint32_t a0, uint32_t a1, uint32_t a2, uint32_t a3,
    uint32_t b0, uint32_t b1)
{
    asm volatile(
        "mma.sync.aligned.m16n8k16.row.col.f32.f16.f16.f32 "
        "{%0,%1,%2,%3},{%4,%5,%6,%7},{%8,%9},{%0,%1,%2,%3};"
        : "+f"(c[0]), "+f"(c[1]), "+f"(c[2]), "+f"(c[3])
        : "r"(a0), "r"(a1), "r"(a2), "r"(a3), "r"(b0), "r"(b1));
}

__device__ __forceinline__ uint32_t pack_h2(float lo, float hi) {
    __half2 h = __floats2half2_rn(lo, hi);
    return *(uint32_t*)&h;
}

__device__ __forceinline__ void cpa16(uint32_t dst_smem, const void* src) {
    asm volatile("cp.async.cg.shared.global [%0], [%1], 16;"
                 :: "r"(dst_smem), "l"(src));
}
__device__ __forceinline__ void cpa_commit() {
    asm volatile("cp.async.commit_group;");
}
template<int N>
__device__ __forceinline__ void cpa_wait() {
    asm volatile("cp.async.wait_group %0;" :: "n"(N));
}

// ---------------------------------------------------------------------------
// Convert fp32 -> fp16
// ---------------------------------------------------------------------------
__global__ void cvt_h(const float* __restrict__ src, __half* __restrict__ dst,
                      int n4)
{
    for (int i = blockIdx.x * blockDim.x + threadIdx.x; i < n4;
         i += gridDim.x * blockDim.x) {
        float4 v = ((const float4*)src)[i];
        ((uint2*)dst)[i] = make_uint2(pack_h2(v.x, v.y), pack_h2(v.z, v.w));
    }
}

__global__ void cvt_h_w(const float* __restrict__ s0, __half* __restrict__ d0,
                        const float* __restrict__ s1, __half* __restrict__ d1,
                        const float* __restrict__ s2, __half* __restrict__ d2,
                        const float* __restrict__ s3, __half* __restrict__ d3,
                        int n4)
{
    const float* src; __half* dst;
    if (blockIdx.z == 0)      { src = s0; dst = d0; }
    else if (blockIdx.z == 1) { src = s1; dst = d1; }
    else if (blockIdx.z == 2) { src = s2; dst = d2; }
    else                      { src = s3; dst = d3; }
    for (int i = blockIdx.x * blockDim.x + threadIdx.x; i < n4;
         i += gridDim.x * blockDim.x) {
        float4 v = ((const float4*)src)[i];
        ((uint2*)dst)[i] = make_uint2(pack_h2(v.x, v.y), pack_h2(v.z, v.w));
    }
}

// ---------------------------------------------------------------------------
// FP16 GEMM (mma.sync m16n8k16, f32 acc), 64x64 warp tiles, 128 threads,
// BK=32 halves, 3-stage cp.async, ONE barrier per chunk.
// mode 0: plain f32 out row-major (O projection).
// mode 1: Q -> RoPE+QSCALE, half [h][s][hd].
// mode 2: K -> RoPE, half [h][s][hd].
// mode 3: V -> half TRANSPOSED per 32-key tile: [h][t32][d64][key32].
// ---------------------------------------------------------------------------
#define GBK   32
#define GSA   20
#define GSTW  (128 * GSA)
#define GSTB  (2 * GSTW * 4)
#define GSMEM (3 * GSTB)

__global__ void __launch_bounds__(128) gemm_h(
    const __half* __restrict__ A,
    const __half* __restrict__ W0, const __half* __restrict__ W1,
    const __half* __restrict__ W2,
    void* __restrict__ out0v, void* __restrict__ out1v,
    void* __restrict__ out2v,
    const float* __restrict__ cosT, const float* __restrict__ sinT,
    int mode0)
{
    extern __shared__ uint32_t gsm[];

    const __half* W; void* outv; int mode;
    if (blockIdx.z == 0)      { W = W0; outv = out0v; mode = mode0; }
    else if (blockIdx.z == 1) { W = W1; outv = out1v; mode = 2; }
    else                      { W = W2; outv = out2v; mode = 3; }

    const int tid  = threadIdx.x;
    const int lane = tid & 31;
    const int wid  = tid >> 5;
    const int wm   = wid >> 1;
    const int wn   = wid & 1;
    const int g4   = lane >> 2;
    const int t4   = lane & 3;

    const int mBase = blockIdx.y * 128;
    const int nBase = blockIdx.x * 128;

    const uint32_t smemu = (uint32_t)__cvta_generic_to_shared(gsm);

    auto prefetch = [&](int s, int t) {
        const int koff = t * GBK;
        const uint32_t abase = smemu + s * GSTB;
        const uint32_t bbase = abase + GSTW * 4;
#pragma unroll
        for (int j = 0; j < 4; j++) {
            const int idx = tid + j * 128;       // 0..511
            const int r = idx >> 2, c16 = idx & 3;
            cpa16(abase + (r * GSA + c16 * 4) * 4,
                  A + (size_t)(mBase + r) * DIM + koff + c16 * 8);
            cpa16(bbase + (r * GSA + c16 * 4) * 4,
                  W + (size_t)(nBase + r) * DIM + koff + c16 * 8);
        }
    };

    float c[4][8][4];
#pragma unroll
    for (int mt = 0; mt < 4; mt++)
#pragma unroll
        for (int nt = 0; nt < 8; nt++)
#pragma unroll
            for (int i = 0; i < 4; i++) c[mt][nt][i] = 0.f;

    const int NT = DIM / GBK;
    prefetch(0, 0); cpa_commit();
    prefetch(1, 1); cpa_commit();

    for (int t = 0; t < NT; t++) {
        if (t + 1 < NT) cpa_wait<1>(); else cpa_wait<0>();
        __syncthreads();

        if (t + 2 < NT) { prefetch((t + 2) % 3, t + 2); cpa_commit(); }

        const uint32_t* a_s = gsm + (t % 3) * (GSTB / 4);
        const uint32_t* b_s = a_s + GSTW;
#pragma unroll
        for (int ks = 0; ks < 2; ks++) {
            const int j = ks * 8 + t4;
            uint32_t af[4][4], bf[8][2];
#pragma unroll
            for (int mt = 0; mt < 4; mt++) {
                const int r = wm * 64 + mt * 16 + g4;
                af[mt][0] = a_s[r * GSA + j];
                af[mt][1] = a_s[(r + 8) * GSA + j];
                af[mt][2] = a_s[r * GSA + j + 4];
                af[mt][3] = a_s[(r + 8) * GSA + j + 4];
            }
#pragma unroll
            for (int nt = 0; nt < 8; nt++) {
                const int r = wn * 64 + nt * 8 + g4;
                bf[nt][0] = b_s[r * GSA + j];
                bf[nt][1] = b_s[r * GSA + j + 4];
            }
#pragma unroll
            for (int mt = 0; mt < 4; mt++)
#pragma unroll
                for (int nt = 0; nt < 8; nt++)
                    mma16h(c[mt][nt], af[mt][0], af[mt][1], af[mt][2], af[mt][3],
                           bf[nt][0], bf[nt][1]);
        }
    }

    // Epilogue
#pragma unroll
    for (int mt = 0; mt < 4; mt++) {
        const int r0 = mBase + wm * 64 + mt * 16 + g4;
#pragma unroll
        for (int nt = 0; nt < 8; nt++) {
            const int colg = nBase + wn * 64 + nt * 8 + (t4 << 1);
            const float* cc = c[mt][nt];
            if (mode == 0) {
                float* out = (float*)outv;
                *(float2*)(out + (size_t)r0 * DIM + colg)       = make_float2(cc[0], cc[1]);
                *(float2*)(out + (size_t)(r0 + 8) * DIM + colg) = make_float2(cc[2], cc[3]);
                continue;
            }
            __half* outh = (__half*)outv;
            const int head = colg >> 6;
            const int hd   = colg & 63;
            const int f    = hd >> 1;
#pragma unroll
            for (int h = 0; h < 2; h++) {
                const int row = r0 + h * 8;
                float e = cc[h * 2 + 0], o = cc[h * 2 + 1];
                if (mode != 3) {
                    const float cth = cosT[row * 32 + f];
                    const float sth = sinT[row * 32 + f];
                    float re = e * cth - o * sth;
                    float ro = e * sth + o * cth;
                    if (mode == 1) { re *= QSCALE; ro *= QSCALE; }
                    // half2 store to [h][s][hd]
                    *(uint32_t*)(outh + ((size_t)head * SEQ + row) * HDIM + hd) =
                        pack_h2(re, ro);
                } else {
                    // V transposed: [h][t32][d64][key32]
                    const int t32 = row >> 5, key = row & 31;
                    __half* vt = outh + (size_t)head * SEQ * HDIM + t32 * 2048;
                    vt[hd * 32 + key]       = __float2half_rn(e);
                    vt[(hd + 1) * 32 + key] = __float2half_rn(o);
                }
            }
        }
    }
}

// ---------------------------------------------------------------------------
// Split-K FP16 flash attention with in-kernel merge.
// Q in registers (A fragments, half2). K [key][d] half smem (row stride 36
// uint32); V^T [d][key] half smem (row stride 28 uint32). Both conflict-free.
// P C-fragments pack DIRECTLY into PV A-fragments (f16 identity) - no shfl.
// ---------------------------------------------------------------------------
#define KT  32
#define KRS 36                              // K smem row stride (uint32)
#define VRS 28                              // V^T smem row stride (uint32)
#define KTILE_SW (KT * KRS)                 // 1152 uint32
#define VTILE_SW (HDIM * VRS)               // 1792 uint32
#define STG_W (KTILE_SW + VTILE_SW)         // 2944 uint32
#define FLASH_SMEM (2 * STG_W * (int)sizeof(uint32_t))   // 23552 B

__global__ void __launch_bounds__(128, 3) flash_split(
    const __half* __restrict__ Q, const __half* __restrict__ K,
    const __half* __restrict__ V,
    float* __restrict__ p0, float* __restrict__ p1,
    float* __restrict__ gm0, float* __restrict__ gl0,
    float* __restrict__ gm1, float* __restrict__ gl1,
    __half* __restrict__ att)
{
    extern __shared__ uint32_t fsm[];

    const int tid  = threadIdx.x;
    const int lane = tid & 31;
    const int wid  = tid >> 5;
    const int g4   = lane >> 2;
    const int t4   = lane & 3;

    const int enc  = gridDim.x - 1 - blockIdx.x;   // longest first
    const int qblk = enc >> 1;
    const int split = enc & 1;
    const int head = blockIdx.y;

    float* part = split ? p1 : p0;
    float* gm   = split ? gm1 : gm0;
    float* gl   = split ? gl1 : gl0;

    const uint32_t smemu = (uint32_t)__cvta_generic_to_shared(fsm);
    const __half* Kh0 = K + (size_t)head * SEQ * HDIM;
    const __half* Vt0 = V + (size_t)head * SEQ * HDIM;

    // prefetch one 32-key tile: K (32 rows x 64 halves) + V^T (64 rows x 32)
    auto prefetch = [&](int buf, int kb) {
        const uint32_t base = smemu + buf * STG_W * 4;
        const __half* Kt = Kh0 + (size_t)kb * 2048;
        const __half* Vt = Vt0 + (size_t)kb * 2048;
#pragma unroll
        for (int j = 0; j < 2; j++) {
            const int idx = tid + j * 128;       // 0..255 K chunks
            const int r = idx >> 3, ck = idx & 7;
            cpa16(base + (r * KRS + ck * 4) * 4, Kt + r * HDIM + ck * 8);
            const int rv = idx >> 2, cv = idx & 3;
            cpa16(base + (KTILE_SW + rv * VRS + cv * 4) * 4, Vt + rv * KT + cv * 8);
        }
    };

    const int half = 2 * (qblk + 1);
    const int t0 = split * half;
    const int t1 = t0 + half;

    prefetch(0, t0); cpa_commit();
    prefetch(1, t0 + 1); cpa_commit();

    // ---- Q A-fragments in registers (one-time global loads) ----
    uint32_t qf[4][2][4];
    {
        const __half* Qh = Q + ((size_t)head * SEQ + qblk * 128 + wid * 32) * HDIM;
#pragma unroll
        for (int ks = 0; ks < 4; ks++)
#pragma unroll
            for (int mh = 0; mh < 2; mh++) {
                const int row0 = mh * 16 + g4;
                const int d0 = ks * 16 + t4 * 2;
                qf[ks][mh][0] = *(const uint32_t*)(Qh + row0 * HDIM + d0);
                qf[ks][mh][1] = *(const uint32_t*)(Qh + (row0 + 8) * HDIM + d0);
                qf[ks][mh][2] = *(const uint32_t*)(Qh + row0 * HDIM + d0 + 8);
                qf[ks][mh][3] = *(const uint32_t*)(Qh + (row0 + 8) * HDIM + d0 + 8);
            }
    }

    float o[2][8][4];
#pragma unroll
    for (int mh = 0; mh < 2; mh++)
#pragma unroll
        for (int nt = 0; nt < 8; nt++)
#pragma unroll
            for (int i = 0; i < 4; i++) o[mh][nt][i] = 0.f;

    float m[2][2], l[2][2];
#pragma unroll
    for (int mh = 0; mh < 2; mh++) {
        m[mh][0] = MINIT; m[mh][1] = MINIT;
        l[mh][0] = 0.f;   l[mh][1] = 0.f;
    }

    for (int kb = t0; kb < t1; kb++) {
        if (kb + 1 < t1) cpa_wait<1>(); else cpa_wait<0>();
        __syncthreads();

        const uint32_t* sK = fsm + (kb & 1) * STG_W;
        const uint32_t* sV = sK + KTILE_SW;

        // ---- S = Q K^T (f16 k16) ----
        float sc[2][4][4];
#pragma unroll
        for (int mh = 0; mh < 2; mh++)
#pragma unroll
            for (int nt = 0; nt < 4; nt++)
#pragma unroll
                for (int i = 0; i < 4; i++) sc[mh][nt][i] = 0.f;

#pragma unroll
        for (int ks = 0; ks < 4; ks++) {
#pragma unroll
            for (int nt = 0; nt < 4; nt++) {
                const int key = nt * 8 + g4;
                const uint32_t b0 = sK[key * KRS + ks * 8 + t4];
                const uint32_t b1 = sK[key * KRS + ks * 8 + t4 + 4];
                mma16h(sc[0][nt], qf[ks][0][0], qf[ks][0][1], qf[ks][0][2], qf[ks][0][3], b0, b1);
                mma16h(sc[1][nt], qf[ks][1][0], qf[ks][1][1], qf[ks][1][2], qf[ks][1][3], b0, b1);
            }
        }

        // ---- causal mask ----
        if (kb >= 4 * qblk) {
#pragma unroll
            for (int mh = 0; mh < 2; mh++) {
                const int r0 = qblk * 128 + wid * 32 + mh * 16 + g4;
                const int r1 = r0 + 8;
#pragma unroll
                for (int nt = 0; nt < 4; nt++) {
                    const int col = kb * KT + nt * 8 + (t4 << 1);
                    if (col > r0)     sc[mh][nt][0] = MMASK;
                    if (col + 1 > r0) sc[mh][nt][1] = MMASK;
                    if (col > r1)     sc[mh][nt][2] = MMASK;
                    if (col + 1 > r1) sc[mh][nt][3] = MMASK;
                }
            }
        }

        // ---- online softmax (log2 domain) ----
        float corr[2][2];
#pragma unroll
        for (int mh = 0; mh < 2; mh++) {
            float mx0 = MMASK, mx1 = MMASK;
#pragma unroll
            for (int nt = 0; nt < 4; nt++) {
                mx0 = fmaxf(mx0, fmaxf(sc[mh][nt][0], sc[mh][nt][1]));
                mx1 = fmaxf(mx1, fmaxf(sc[mh][nt][2], sc[mh][nt][3]));
            }
            mx0 = fmaxf(mx0, __shfl_xor_sync(0xffffffffu, mx0, 1));
            mx0 = fmaxf(mx0, __shfl_xor_sync(0xffffffffu, mx0, 2));
            mx1 = fmaxf(mx1, __shfl_xor_sync(0xffffffffu, mx1, 1));
            mx1 = fmaxf(mx1, __shfl_xor_sync(0xffffffffu, mx1, 2));

            const float mn0 = fmaxf(m[mh][0], mx0);
            const float mn1 = fmaxf(m[mh][1], mx1);
            corr[mh][0] = ex2(m[mh][0] - mn0);
            corr[mh][1] = ex2(m[mh][1] - mn1);
            m[mh][0] = mn0; m[mh][1] = mn1;

            float ls0 = 0.f, ls1 = 0.f;
#pragma unroll
            for (int nt = 0; nt < 4; nt++) {
                sc[mh][nt][0] = ex2(sc[mh][nt][0] - mn0);
                sc[mh][nt][1] = ex2(sc[mh][nt][1] - mn0);
                sc[mh][nt][2] = ex2(sc[mh][nt][2] - mn1);
                sc[mh][nt][3] = ex2(sc[mh][nt][3] - mn1);
                ls0 += sc[mh][nt][0] + sc[mh][nt][1];
                ls1 += sc[mh][nt][2] + sc[mh][nt][3];
            }
            ls0 += __shfl_xor_sync(0xffffffffu, ls0, 1);
            ls0 += __shfl_xor_sync(0xffffffffu, ls0, 2);
            ls1 += __shfl_xor_sync(0xffffffffu, ls1, 1);
            ls1 += __shfl_xor_sync(0xffffffffu, ls1, 2);
            l[mh][0] = l[mh][0] * corr[mh][0] + ls0;
            l[mh][1] = l[mh][1] * corr[mh][1] + ls1;

#pragma unroll
            for (int nt = 0; nt < 8; nt++) {
                o[mh][nt][0] *= corr[mh][0]; o[mh][nt][1] *= corr[mh][0];
                o[mh][nt][2] *= corr[mh][1]; o[mh][nt][3] *= corr[mh][1];
            }
        }

        // ---- O += P V : C-fragment -> A-fragment identity (no shuffles) ----
#pragma unroll
        for (int ks = 0; ks < 2; ks++) {
            uint32_t pa[2][4];
#pragma unroll
            for (int mh = 0; mh < 2; mh++) {
                pa[mh][0] = pack_h2(sc[mh][2 * ks][0],     sc[mh][2 * ks][1]);
                pa[mh][1] = pack_h2(sc[mh][2 * ks][2],     sc[mh][2 * ks][3]);
                pa[mh][2] = pack_h2(sc[mh][2 * ks + 1][0], sc[mh][2 * ks + 1][1]);
                pa[mh][3] = pack_h2(sc[mh][2 * ks + 1][2], sc[mh][2 * ks + 1][3]);
            }
#pragma unroll
            for (int nt = 0; nt < 8; nt++) {
                const int d = nt * 8 + g4;
                const uint32_t b0 = sV[d * VRS + ks * 8 + t4];
                const uint32_t b1 = sV[d * VRS + ks * 8 + t4 + 4];
                mma16h(o[0][nt], pa[0][0], pa[0][1], pa[0][2], pa[0][3], b0, b1);
                mma16h(o[1][nt], pa[1][0], pa[1][1], pa[1][2], pa[1][3], b0, b1);
            }
        }

        __syncthreads();
        if (kb + 2 < t1) { prefetch(kb & 1, kb + 2); cpa_commit(); }
    }

    // ---- write own raw partial + (m, l) ----
#pragma unroll
    for (int mh = 0; mh < 2; mh++) {
        const int r0 = qblk * 128 + wid * 32 + mh * 16 + g4;
#pragma unroll
        for (int nt = 0; nt < 8; nt++) {
            const int col = head * HDIM + nt * 8 + (t4 << 1);
            *(float2*)(part + (size_t)r0 * DIM + col) =
                make_float2(o[mh][nt][0], o[mh][nt][1]);
            *(float2*)(part + (size_t)(r0 + 8) * DIM + col) =
                make_float2(o[mh][nt][2], o[mh][nt][3]);
        }
        if (t4 == 0) {
            gm[head * SEQ + r0]     = m[mh][0];
            gl[head * SEQ + r0]     = l[mh][0];
            gm[head * SEQ + r0 + 8] = m[mh][1];
            gl[head * SEQ + r0 + 8] = l[mh][1];
        }
    }

    // ---- last-CTA-done merge ----
    __threadfence();
    __syncthreads();
    if (tid == 0) {
        const int old = atomicAdd(&g_cnt[head * (SEQ / 128) + qblk], 1);
        ((volatile int*)fsm)[0] = old;
    }
    __syncthreads();
    const int old = ((volatile int*)fsm)[0];
    if (old != 1) return;
    __threadfence();
    if (tid == 0) g_cnt[head * (SEQ / 128) + qblk] = 0;

    const float* po  = split ? p0 : p1;
    const float* gmo = split ? gm0 : gm1;
    const float* glo = split ? gl0 : gl1;

#pragma unroll
    for (int mh = 0; mh < 2; mh++) {
        const int r0 = qblk * 128 + wid * 32 + mh * 16 + g4;
#pragma unroll
        for (int rh = 0; rh < 2; rh++) {
            const int row = r0 + rh * 8;
            const float mOwn = m[mh][rh], lOwn = l[mh][rh];
            const float mOth = gmo[head * SEQ + row];
            const float lOth = glo[head * SEQ + row];
            const float mA = split ? mOth : mOwn;
            const float lA = split ? lOth : lOwn;
            const float mB = split ? mOwn : mOth;
            const float lB = split ? lOwn : lOth;
            const float ms = fmaxf(mA, mB);
            const float wA = ex2(mA - ms), wB = ex2(mB - ms);
            const float inv = 1.f / (lA * wA + lB * wB);
            const float wOwn = split ? wB : wA;
            const float wOth = split ? wA : wB;
#pragma unroll
            for (int nt = 0; nt < 8; nt++) {
                const int col = head * HDIM + nt * 8 + (t4 << 1);
                const float2 ov = *(const float2*)(po + (size_t)row * DIM + col);
                const float x0 = (o[mh][nt][rh * 2 + 0] * wOwn + ov.x * wOth) * inv;
                const float x1 = (o[mh][nt][rh * 2 + 1] * wOwn + ov.y * wOth) * inv;
                *(uint32_t*)(att + (size_t)row * DIM + col) = pack_h2(x0, x1);
            }
        }
    }
}

// ---------------------------------------------------------------------------
// Launch
// ---------------------------------------------------------------------------
extern "C" void kernel_launch(void* const* d_in, const int* in_sizes, int n_in,
                              void* d_out, int out_size)
{
    const float* x    = (const float*)d_in[0];
    const float* cosT = (const float*)d_in[1];
    const float* sinT = (const float*)d_in[2];
    const float* wq   = (const float*)d_in[4];
    const float* wk   = (const float*)d_in[5];
    const float* wv   = (const float*)d_in[6];
    const float* wo   = (const float*)d_in[7];
    float* out = (float*)d_out;

    float *p0, *p1, *m0, *l0, *m1, *l1;
    __half *qh, *kh, *vt, *ap, *xh, *wqh, *wkh, *wvh, *woh;
    cudaGetSymbolAddress((void**)&qh, g_qh);
    cudaGetSymbolAddress((void**)&kh, g_kh);
    cudaGetSymbolAddress((void**)&vt, g_vt);
    cudaGetSymbolAddress((void**)&ap, g_att);
    cudaGetSymbolAddress((void**)&xh, g_xh);
    cudaGetSymbolAddress((void**)&wqh, g_wqh);
    cudaGetSymbolAddress((void**)&wkh, g_wkh);
    cudaGetSymbolAddress((void**)&wvh, g_wvh);
    cudaGetSymbolAddress((void**)&woh, g_woh);
    cudaGetSymbolAddress((void**)&p0, g_p0);
    cudaGetSymbolAddress((void**)&p1, g_p1);
    cudaGetSymbolAddress((void**)&m0, g_m0);
    cudaGetSymbolAddress((void**)&l0, g_l0);
    cudaGetSymbolAddress((void**)&m1, g_m1);
    cudaGetSymbolAddress((void**)&l1, g_l1);

    cudaFuncSetAttribute(flash_split,
                         cudaFuncAttributeMaxDynamicSharedMemorySize, FLASH_SMEM);
    cudaFuncSetAttribute(gemm_h,
                         cudaFuncAttributeMaxDynamicSharedMemorySize, GSMEM);

    // Convert inputs to fp16 once
    cvt_h<<<512, 256>>>(x, xh, SEQ * DIM / 4);
    dim3 wgrid(128, 1, 4);
    cvt_h_w<<<wgrid, 256>>>(wq, wqh, wk, wkh, wv, wvh, wo, woh, DIM * DIM / 4);

    // Fused QKV projections (fp16 MMA; Q/K half [h][s][hd], V^T half tiles)
    dim3 ggrid(DIM / 128, SEQ / 128, 3);
    gemm_h<<<ggrid, 128, GSMEM>>>(xh, wqh, wkh, wvh, qh, kh, vt, cosT, sinT, 1);

    // Split-K fp16 flash with in-kernel merge
    dim3 fgrid(2 * (SEQ / 128), NH);
    flash_split<<<fgrid, 128, FLASH_SMEM>>>(qh, kh, vt, p0, p1, m0, l0, m1, l1, ap);

    // Output projection (fp16 MMA, fp32 out)
    dim3 ogrid(DIM / 128, SEQ / 128, 1);
    gemm_h<<<ogrid, 128, GSMEM>>>(ap, woh, woh, woh, out, out, out, cosT, sinT, 0);
}

// round 16
// speedup vs baseline: 1.7463x; 1.0146x over previous
#include <cuda_runtime.h>
#include <cuda_fp16.h>
#include <math.h>
#include <stdint.h>

#define SEQ 4096
#define DIM 1024
#define NH  16
#define HDIM 64

// Scratch
__device__ __half g_qh[NH * SEQ * HDIM];  // [h][s][hd] half, pre-scaled
__device__ __half g_kh[NH * SEQ * HDIM];  // [h][s][hd] half
__device__ __half g_vt[NH * SEQ * HDIM];  // [h][tile32][d64][key32] half (transposed)
__device__ __half g_att[SEQ * DIM];       // [s][d] half (merged attention out)
__device__ __half g_xh[SEQ * DIM];        // x as half
__device__ __half g_wqh[DIM * DIM];       // weights as half
__device__ __half g_wkh[DIM * DIM];
__device__ __half g_wvh[DIM * DIM];
__device__ __half g_woh[DIM * DIM];
// split-K partials (raw fp32)
__device__ float g_p0[SEQ * DIM];
__device__ float g_p1[SEQ * DIM];
__device__ float g_m0[NH * SEQ];
__device__ float g_l0[NH * SEQ];
__device__ float g_m1[NH * SEQ];
__device__ float g_l1[NH * SEQ];
// merge counters (zero-init; merger resets -> replay-safe)
__device__ int g_cnt[NH * (SEQ / 128)];

#define QSCALE (0.125f * 1.4426950408889634f)   // 1/sqrt(64) * log2(e)
#define MINIT  (-1.6e38f)
#define MMASK  (-3.2e38f)

__device__ __forceinline__ float ex2(float x) {
    float r;
    asm("ex2.approx.f32 %0, %1;" : "=f"(r) : "f"(x));
    return r;
}

// f16 m16n8k16, f32 accumulate
__device__ __forceinline__ void mma16h(float c[4],
    uint32_t a0, uint32_t a1, uint32_t a2, uint32_t a3,
    uint32_t b0, uint32_t b1)
{
    asm volatile(
        "mma.sync.aligned.m16n8k16.row.col.f32.f16.f16.f32 "
        "{%0,%1,%2,%3},{%4,%5,%6,%7},{%8,%9},{%0,%1,%2,%3};"
        : "+f"(c[0]), "+f"(c[1]), "+f"(c[2]), "+f"(c[3])
        : "r"(a0), "r"(a1), "r"(a2), "r"(a3), "r"(b0), "r"(b1));
}

__device__ __forceinline__ void ldsm4(uint32_t r[4], uint32_t addr) {
    asm volatile(
        "ldmatrix.sync.aligned.m8n8.x4.shared.b16 {%0,%1,%2,%3}, [%4];"
        : "=r"(r[0]), "=r"(r[1]), "=r"(r[2]), "=r"(r[3]) : "r"(addr));
}

__device__ __forceinline__ uint32_t pack_h2(float lo, float hi) {
    __half2 h = __floats2half2_rn(lo, hi);
    return *(uint32_t*)&h;
}

__device__ __forceinline__ void cpa16(uint32_t dst_smem, const void* src) {
    asm volatile("cp.async.cg.shared.global [%0], [%1], 16;"
                 :: "r"(dst_smem), "l"(src));
}
__device__ __forceinline__ void cpa_commit() {
    asm volatile("cp.async.commit_group;");
}
template<int N>
__device__ __forceinline__ void cpa_wait() {
    asm volatile("cp.async.wait_group %0;" :: "n"(N));
}

// ---------------------------------------------------------------------------
// Convert fp32 -> fp16
// ---------------------------------------------------------------------------
__global__ void cvt_h(const float* __restrict__ src, __half* __restrict__ dst,
                      int n4)
{
    for (int i = blockIdx.x * blockDim.x + threadIdx.x; i < n4;
         i += gridDim.x * blockDim.x) {
        float4 v = ((const float4*)src)[i];
        ((uint2*)dst)[i] = make_uint2(pack_h2(v.x, v.y), pack_h2(v.z, v.w));
    }
}

__global__ void cvt_h_w(const float* __restrict__ s0, __half* __restrict__ d0,
                        const float* __restrict__ s1, __half* __restrict__ d1,
                        const float* __restrict__ s2, __half* __restrict__ d2,
                        const float* __restrict__ s3, __half* __restrict__ d3,
                        int n4)
{
    const float* src; __half* dst;
    if (blockIdx.z == 0)      { src = s0; dst = d0; }
    else if (blockIdx.z == 1) { src = s1; dst = d1; }
    else if (blockIdx.z == 2) { src = s2; dst = d2; }
    else                      { src = s3; dst = d3; }
    for (int i = blockIdx.x * blockDim.x + threadIdx.x; i < n4;
         i += gridDim.x * blockDim.x) {
        float4 v = ((const float4*)src)[i];
        ((uint2*)dst)[i] = make_uint2(pack_h2(v.x, v.y), pack_h2(v.z, v.w));
    }
}

// ---------------------------------------------------------------------------
// FP16 GEMM (mma.sync m16n8k16 + ldmatrix), 64x64 warp tiles, 128 threads,
// BK=32 halves, 3-stage cp.async, ONE barrier per chunk.
// mode 0: plain f32 out; 1: Q RoPE+QSCALE half; 2: K RoPE half;
// 3: V half transposed per 32-key tile [h][t32][d64][key32].
// ---------------------------------------------------------------------------
#define GBK   32
#define GSA   20
#define GSTW  (128 * GSA)
#define GSTB  (2 * GSTW * 4)
#define GSMEM (3 * GSTB)

__global__ void __launch_bounds__(128) gemm_h(
    const __half* __restrict__ A,
    const __half* __restrict__ W0, const __half* __restrict__ W1,
    const __half* __restrict__ W2,
    void* __restrict__ out0v, void* __restrict__ out1v,
    void* __restrict__ out2v,
    const float* __restrict__ cosT, const float* __restrict__ sinT,
    int mode0)
{
    extern __shared__ uint32_t gsm[];

    const __half* W; void* outv; int mode;
    if (blockIdx.z == 0)      { W = W0; outv = out0v; mode = mode0; }
    else if (blockIdx.z == 1) { W = W1; outv = out1v; mode = 2; }
    else                      { W = W2; outv = out2v; mode = 3; }

    const int tid  = threadIdx.x;
    const int lane = tid & 31;
    const int wid  = tid >> 5;
    const int wm   = wid >> 1;
    const int wn   = wid & 1;
    const int g4   = lane >> 2;
    const int t4   = lane & 3;

    const int mBase = blockIdx.y * 128;
    const int nBase = blockIdx.x * 128;

    const uint32_t smemu = (uint32_t)__cvta_generic_to_shared(gsm);

    // ldmatrix lane address components
    const int rowA = lane & 15;                      // A: row within 16-block
    const int khA  = (lane >> 4) << 2;               // A: k-half (uint32 units)
    const int rowB = (lane & 7) + ((lane >> 4) << 3);// B: row within 16-block
    const int khB  = ((lane >> 3) & 1) << 2;         // B: k-half

    auto prefetch = [&](int s, int t) {
        const int koff = t * GBK;
        const uint32_t abase = smemu + s * GSTB;
        const uint32_t bbase = abase + GSTW * 4;
#pragma unroll
        for (int j = 0; j < 4; j++) {
            const int idx = tid + j * 128;       // 0..511
            const int r = idx >> 2, c16 = idx & 3;
            cpa16(abase + (r * GSA + c16 * 4) * 4,
                  A + (size_t)(mBase + r) * DIM + koff + c16 * 8);
            cpa16(bbase + (r * GSA + c16 * 4) * 4,
                  W + (size_t)(nBase + r) * DIM + koff + c16 * 8);
        }
    };

    float c[4][8][4];
#pragma unroll
    for (int mt = 0; mt < 4; mt++)
#pragma unroll
        for (int nt = 0; nt < 8; nt++)
#pragma unroll
            for (int i = 0; i < 4; i++) c[mt][nt][i] = 0.f;

    const int NT = DIM / GBK;
    prefetch(0, 0); cpa_commit();
    prefetch(1, 1); cpa_commit();

    for (int t = 0; t < NT; t++) {
        if (t + 1 < NT) cpa_wait<1>(); else cpa_wait<0>();
        __syncthreads();

        if (t + 2 < NT) { prefetch((t + 2) % 3, t + 2); cpa_commit(); }

        const uint32_t abase = smemu + (t % 3) * GSTB;
        const uint32_t bbase = abase + GSTW * 4;
#pragma unroll
        for (int ks = 0; ks < 2; ks++) {
            uint32_t af[4][4];
#pragma unroll
            for (int mt = 0; mt < 4; mt++)
                ldsm4(af[mt], abase +
                      ((wm * 64 + mt * 16 + rowA) * GSA + ks * 8 + khA) * 4);
#pragma unroll
            for (int ntp = 0; ntp < 4; ntp++) {
                uint32_t bb[4];
                ldsm4(bb, bbase +
                      ((wn * 64 + ntp * 16 + rowB) * GSA + ks * 8 + khB) * 4);
#pragma unroll
                for (int mt = 0; mt < 4; mt++) {
                    mma16h(c[mt][2 * ntp],     af[mt][0], af[mt][1], af[mt][2], af[mt][3], bb[0], bb[1]);
                    mma16h(c[mt][2 * ntp + 1], af[mt][0], af[mt][1], af[mt][2], af[mt][3], bb[2], bb[3]);
                }
            }
        }
    }

    // Epilogue
#pragma unroll
    for (int mt = 0; mt < 4; mt++) {
        const int r0 = mBase + wm * 64 + mt * 16 + g4;
#pragma unroll
        for (int nt = 0; nt < 8; nt++) {
            const int colg = nBase + wn * 64 + nt * 8 + (t4 << 1);
            const float* cc = c[mt][nt];
            if (mode == 0) {
                float* out = (float*)outv;
                *(float2*)(out + (size_t)r0 * DIM + colg)       = make_float2(cc[0], cc[1]);
                *(float2*)(out + (size_t)(r0 + 8) * DIM + colg) = make_float2(cc[2], cc[3]);
                continue;
            }
            __half* outh = (__half*)outv;
            const int head = colg >> 6;
            const int hd   = colg & 63;
            const int f    = hd >> 1;
#pragma unroll
            for (int h = 0; h < 2; h++) {
                const int row = r0 + h * 8;
                float e = cc[h * 2 + 0], o = cc[h * 2 + 1];
                if (mode != 3) {
                    const float cth = cosT[row * 32 + f];
                    const float sth = sinT[row * 32 + f];
                    float re = e * cth - o * sth;
                    float ro = e * sth + o * cth;
                    if (mode == 1) { re *= QSCALE; ro *= QSCALE; }
                    *(uint32_t*)(outh + ((size_t)head * SEQ + row) * HDIM + hd) =
                        pack_h2(re, ro);
                } else {
                    const int t32 = row >> 5, key = row & 31;
                    __half* vt = outh + (size_t)head * SEQ * HDIM + t32 * 2048;
                    vt[hd * 32 + key]       = __float2half_rn(e);
                    vt[(hd + 1) * 32 + key] = __float2half_rn(o);
                }
            }
        }
    }
}

// ---------------------------------------------------------------------------
// Split-K FP16 flash attention with in-kernel merge, ldmatrix operand loads.
// ---------------------------------------------------------------------------
#define KT  32
#define KRS 36
#define VRS 28
#define KTILE_SW (KT * KRS)
#define VTILE_SW (HDIM * VRS)
#define STG_W (KTILE_SW + VTILE_SW)
#define FLASH_SMEM (2 * STG_W * (int)sizeof(uint32_t))

__global__ void __launch_bounds__(128, 3) flash_split(
    const __half* __restrict__ Q, const __half* __restrict__ K,
    const __half* __restrict__ V,
    float* __restrict__ p0, float* __restrict__ p1,
    float* __restrict__ gm0, float* __restrict__ gl0,
    float* __restrict__ gm1, float* __restrict__ gl1,
    __half* __restrict__ att)
{
    extern __shared__ uint32_t fsm[];

    const int tid  = threadIdx.x;
    const int lane = tid & 31;
    const int wid  = tid >> 5;
    const int g4   = lane >> 2;
    const int t4   = lane & 3;

    const int enc  = gridDim.x - 1 - blockIdx.x;
    const int qblk = enc >> 1;
    const int split = enc & 1;
    const int head = blockIdx.y;

    float* part = split ? p1 : p0;
    float* gm   = split ? gm1 : gm0;
    float* gl   = split ? gl1 : gl0;

    const uint32_t smemu = (uint32_t)__cvta_generic_to_shared(fsm);
    const __half* Kh0 = K + (size_t)head * SEQ * HDIM;
    const __half* Vt0 = V + (size_t)head * SEQ * HDIM;

    // ldmatrix lane address components (B pattern)
    const int rowB = (lane & 7) + ((lane >> 4) << 3);
    const int khB  = ((lane >> 3) & 1) << 2;

    auto prefetch = [&](int buf, int kb) {
        const uint32_t base = smemu + buf * STG_W * 4;
        const __half* Kt = Kh0 + (size_t)kb * 2048;
        const __half* Vt = Vt0 + (size_t)kb * 2048;
#pragma unroll
        for (int j = 0; j < 2; j++) {
            const int idx = tid + j * 128;
            const int r = idx >> 3, ck = idx & 7;
            cpa16(base + (r * KRS + ck * 4) * 4, Kt + r * HDIM + ck * 8);
            const int rv = idx >> 2, cv = idx & 3;
            cpa16(base + (KTILE_SW + rv * VRS + cv * 4) * 4, Vt + rv * KT + cv * 8);
        }
    };

    const int half = 2 * (qblk + 1);
    const int t0 = split * half;
    const int t1 = t0 + half;

    prefetch(0, t0); cpa_commit();
    prefetch(1, t0 + 1); cpa_commit();

    // Q A-fragments in registers (one-time global loads)
    uint32_t qf[4][2][4];
    {
        const __half* Qh = Q + ((size_t)head * SEQ + qblk * 128 + wid * 32) * HDIM;
#pragma unroll
        for (int ks = 0; ks < 4; ks++)
#pragma unroll
            for (int mh = 0; mh < 2; mh++) {
                const int row0 = mh * 16 + g4;
                const int d0 = ks * 16 + t4 * 2;
                qf[ks][mh][0] = *(const uint32_t*)(Qh + row0 * HDIM + d0);
                qf[ks][mh][1] = *(const uint32_t*)(Qh + (row0 + 8) * HDIM + d0);
                qf[ks][mh][2] = *(const uint32_t*)(Qh + row0 * HDIM + d0 + 8);
                qf[ks][mh][3] = *(const uint32_t*)(Qh + (row0 + 8) * HDIM + d0 + 8);
            }
    }

    float o[2][8][4];
#pragma unroll
    for (int mh = 0; mh < 2; mh++)
#pragma unroll
        for (int nt = 0; nt < 8; nt++)
#pragma unroll
            for (int i = 0; i < 4; i++) o[mh][nt][i] = 0.f;

    float m[2][2], l[2][2];
#pragma unroll
    for (int mh = 0; mh < 2; mh++) {
        m[mh][0] = MINIT; m[mh][1] = MINIT;
        l[mh][0] = 0.f;   l[mh][1] = 0.f;
    }

    for (int kb = t0; kb < t1; kb++) {
        if (kb + 1 < t1) cpa_wait<1>(); else cpa_wait<0>();
        __syncthreads();

        const uint32_t kbase = smemu + (kb & 1) * STG_W * 4;
        const uint32_t vbase = kbase + KTILE_SW * 4;

        // ---- S = Q K^T ----
        float sc[2][4][4];
#pragma unroll
        for (int mh = 0; mh < 2; mh++)
#pragma unroll
            for (int nt = 0; nt < 4; nt++)
#pragma unroll
                for (int i = 0; i < 4; i++) sc[mh][nt][i] = 0.f;

#pragma unroll
        for (int ks = 0; ks < 4; ks++) {
#pragma unroll
            for (int ntp = 0; ntp < 2; ntp++) {
                uint32_t bb[4];
                ldsm4(bb, kbase + ((ntp * 16 + rowB) * KRS + ks * 8 + khB) * 4);
                mma16h(sc[0][2 * ntp],     qf[ks][0][0], qf[ks][0][1], qf[ks][0][2], qf[ks][0][3], bb[0], bb[1]);
                mma16h(sc[1][2 * ntp],     qf[ks][1][0], qf[ks][1][1], qf[ks][1][2], qf[ks][1][3], bb[0], bb[1]);
                mma16h(sc[0][2 * ntp + 1], qf[ks][0][0], qf[ks][0][1], qf[ks][0][2], qf[ks][0][3], bb[2], bb[3]);
                mma16h(sc[1][2 * ntp + 1], qf[ks][1][0], qf[ks][1][1], qf[ks][1][2], qf[ks][1][3], bb[2], bb[3]);
            }
        }

        // ---- causal mask ----
        if (kb >= 4 * qblk) {
#pragma unroll
            for (int mh = 0; mh < 2; mh++) {
                const int r0 = qblk * 128 + wid * 32 + mh * 16 + g4;
                const int r1 = r0 + 8;
#pragma unroll
                for (int nt = 0; nt < 4; nt++) {
                    const int col = kb * KT + nt * 8 + (t4 << 1);
                    if (col > r0)     sc[mh][nt][0] = MMASK;
                    if (col + 1 > r0) sc[mh][nt][1] = MMASK;
                    if (col > r1)     sc[mh][nt][2] = MMASK;
                    if (col + 1 > r1) sc[mh][nt][3] = MMASK;
                }
            }
        }

        // ---- online softmax (log2 domain) ----
        float corr[2][2];
#pragma unroll
        for (int mh = 0; mh < 2; mh++) {
            float mx0 = MMASK, mx1 = MMASK;
#pragma unroll
            for (int nt = 0; nt < 4; nt++) {
                mx0 = fmaxf(mx0, fmaxf(sc[mh][nt][0], sc[mh][nt][1]));
                mx1 = fmaxf(mx1, fmaxf(sc[mh][nt][2], sc[mh][nt][3]));
            }
            mx0 = fmaxf(mx0, __shfl_xor_sync(0xffffffffu, mx0, 1));
            mx0 = fmaxf(mx0, __shfl_xor_sync(0xffffffffu, mx0, 2));
            mx1 = fmaxf(mx1, __shfl_xor_sync(0xffffffffu, mx1, 1));
            mx1 = fmaxf(mx1, __shfl_xor_sync(0xffffffffu, mx1, 2));

            const float mn0 = fmaxf(m[mh][0], mx0);
            const float mn1 = fmaxf(m[mh][1], mx1);
            corr[mh][0] = ex2(m[mh][0] - mn0);
            corr[mh][1] = ex2(m[mh][1] - mn1);
            m[mh][0] = mn0; m[mh][1] = mn1;

            float ls0 = 0.f, ls1 = 0.f;
#pragma unroll
            for (int nt = 0; nt < 4; nt++) {
                sc[mh][nt][0] = ex2(sc[mh][nt][0] - mn0);
                sc[mh][nt][1] = ex2(sc[mh][nt][1] - mn0);
                sc[mh][nt][2] = ex2(sc[mh][nt][2] - mn1);
                sc[mh][nt][3] = ex2(sc[mh][nt][3] - mn1);
                ls0 += sc[mh][nt][0] + sc[mh][nt][1];
                ls1 += sc[mh][nt][2] + sc[mh][nt][3];
            }
            ls0 += __shfl_xor_sync(0xffffffffu, ls0, 1);
            ls0 += __shfl_xor_sync(0xffffffffu, ls0, 2);
            ls1 += __shfl_xor_sync(0xffffffffu, ls1, 1);
            ls1 += __shfl_xor_sync(0xffffffffu, ls1, 2);
            l[mh][0] = l[mh][0] * corr[mh][0] + ls0;
            l[mh][1] = l[mh][1] * corr[mh][1] + ls1;

#pragma unroll
            for (int nt = 0; nt < 8; nt++) {
                o[mh][nt][0] *= corr[mh][0]; o[mh][nt][1] *= corr[mh][0];
                o[mh][nt][2] *= corr[mh][1]; o[mh][nt][3] *= corr[mh][1];
            }
        }

        // ---- O += P V : C->A fragment identity + ldmatrix V^T ----
#pragma unroll
        for (int ks = 0; ks < 2; ks++) {
            uint32_t pa[2][4];
#pragma unroll
            for (int mh = 0; mh < 2; mh++) {
                pa[mh][0] = pack_h2(sc[mh][2 * ks][0],     sc[mh][2 * ks][1]);
                pa[mh][1] = pack_h2(sc[mh][2 * ks][2],     sc[mh][2 * ks][3]);
                pa[mh][2] = pack_h2(sc[mh][2 * ks + 1][0], sc[mh][2 * ks + 1][1]);
                pa[mh][3] = pack_h2(sc[mh][2 * ks + 1][2], sc[mh][2 * ks + 1][3]);
            }
#pragma unroll
            for (int ntp = 0; ntp < 4; ntp++) {
                uint32_t bb[4];
                ldsm4(bb, vbase + ((ntp * 16 + rowB) * VRS + ks * 8 + khB) * 4);
                mma16h(o[0][2 * ntp],     pa[0][0], pa[0][1], pa[0][2], pa[0][3], bb[0], bb[1]);
                mma16h(o[1][2 * ntp],     pa[1][0], pa[1][1], pa[1][2], pa[1][3], bb[0], bb[1]);
                mma16h(o[0][2 * ntp + 1], pa[0][0], pa[0][1], pa[0][2], pa[0][3], bb[2], bb[3]);
                mma16h(o[1][2 * ntp + 1], pa[1][0], pa[1][1], pa[1][2], pa[1][3], bb[2], bb[3]);
            }
        }

        __syncthreads();
        if (kb + 2 < t1) { prefetch(kb & 1, kb + 2); cpa_commit(); }
    }

    // ---- write own raw partial + (m, l) ----
#pragma unroll
    for (int mh = 0; mh < 2; mh++) {
        const int r0 = qblk * 128 + wid * 32 + mh * 16 + g4;
#pragma unroll
        for (int nt = 0; nt < 8; nt++) {
            const int col = head * HDIM + nt * 8 + (t4 << 1);
            *(float2*)(part + (size_t)r0 * DIM + col) =
                make_float2(o[mh][nt][0], o[mh][nt][1]);
            *(float2*)(part + (size_t)(r0 + 8) * DIM + col) =
                make_float2(o[mh][nt][2], o[mh][nt][3]);
        }
        if (t4 == 0) {
            gm[head * SEQ + r0]     = m[mh][0];
            gl[head * SEQ + r0]     = l[mh][0];
            gm[head * SEQ + r0 + 8] = m[mh][1];
            gl[head * SEQ + r0 + 8] = l[mh][1];
        }
    }

    // ---- last-CTA-done merge ----
    __threadfence();
    __syncthreads();
    if (tid == 0) {
        const int old = atomicAdd(&g_cnt[head * (SEQ / 128) + qblk], 1);
        ((volatile int*)fsm)[0] = old;
    }
    __syncthreads();
    const int old = ((volatile int*)fsm)[0];
    if (old != 1) return;
    __threadfence();
    if (tid == 0) g_cnt[head * (SEQ / 128) + qblk] = 0;

    const float* po  = split ? p0 : p1;
    const float* gmo = split ? gm0 : gm1;
    const float* glo = split ? gl0 : gl1;

#pragma unroll
    for (int mh = 0; mh < 2; mh++) {
        const int r0 = qblk * 128 + wid * 32 + mh * 16 + g4;
#pragma unroll
        for (int rh = 0; rh < 2; rh++) {
            const int row = r0 + rh * 8;
            const float mOwn = m[mh][rh], lOwn = l[mh][rh];
            const float mOth = gmo[head * SEQ + row];
            const float lOth = glo[head * SEQ + row];
            const float mA = split ? mOth : mOwn;
            const float lA = split ? lOth : lOwn;
            const float mB = split ? mOwn : mOth;
            const float lB = split ? lOwn : lOth;
            const float ms = fmaxf(mA, mB);
            const float wA = ex2(mA - ms), wB = ex2(mB - ms);
            const float inv = 1.f / (lA * wA + lB * wB);
            const float wOwn = split ? wB : wA;
            const float wOth = split ? wA : wB;
#pragma unroll
            for (int nt = 0; nt < 8; nt++) {
                const int col = head * HDIM + nt * 8 + (t4 << 1);
                const float2 ov = *(const float2*)(po + (size_t)row * DIM + col);
                const float x0 = (o[mh][nt][rh * 2 + 0] * wOwn + ov.x * wOth) * inv;
                const float x1 = (o[mh][nt][rh * 2 + 1] * wOwn + ov.y * wOth) * inv;
                *(uint32_t*)(att + (size_t)row * DIM + col) = pack_h2(x0, x1);
            }
        }
    }
}

// ---------------------------------------------------------------------------
// Launch
// ---------------------------------------------------------------------------
extern "C" void kernel_launch(void* const* d_in, const int* in_sizes, int n_in,
                              void* d_out, int out_size)
{
    const float* x    = (const float*)d_in[0];
    const float* cosT = (const float*)d_in[1];
    const float* sinT = (const float*)d_in[2];
    const float* wq   = (const float*)d_in[4];
    const float* wk   = (const float*)d_in[5];
    const float* wv   = (const float*)d_in[6];
    const float* wo   = (const float*)d_in[7];
    float* out = (float*)d_out;

    float *p0, *p1, *m0, *l0, *m1, *l1;
    __half *qh, *kh, *vt, *ap, *xh, *wqh, *wkh, *wvh, *woh;
    cudaGetSymbolAddress((void**)&qh, g_qh);
    cudaGetSymbolAddress((void**)&kh, g_kh);
    cudaGetSymbolAddress((void**)&vt, g_vt);
    cudaGetSymbolAddress((void**)&ap, g_att);
    cudaGetSymbolAddress((void**)&xh, g_xh);
    cudaGetSymbolAddress((void**)&wqh, g_wqh);
    cudaGetSymbolAddress((void**)&wkh, g_wkh);
    cudaGetSymbolAddress((void**)&wvh, g_wvh);
    cudaGetSymbolAddress((void**)&woh, g_woh);
    cudaGetSymbolAddress((void**)&p0, g_p0);
    cudaGetSymbolAddress((void**)&p1, g_p1);
    cudaGetSymbolAddress((void**)&m0, g_m0);
    cudaGetSymbolAddress((void**)&l0, g_l0);
    cudaGetSymbolAddress((void**)&m1, g_m1);
    cudaGetSymbolAddress((void**)&l1, g_l1);

    cudaFuncSetAttribute(flash_split,
                         cudaFuncAttributeMaxDynamicSharedMemorySize, FLASH_SMEM);
    cudaFuncSetAttribute(gemm_h,
                         cudaFuncAttributeMaxDynamicSharedMemorySize, GSMEM);

    // Convert inputs to fp16 once
    cvt_h<<<512, 256>>>(x, xh, SEQ * DIM / 4);
    dim3 wgrid(128, 1, 4);
    cvt_h_w<<<wgrid, 256>>>(wq, wqh, wk, wkh, wv, wvh, wo, woh, DIM * DIM / 4);

    // Fused QKV projections
    dim3 ggrid(DIM / 128, SEQ / 128, 3);
    gemm_h<<<ggrid, 128, GSMEM>>>(xh, wqh, wkh, wvh, qh, kh, vt, cosT, sinT, 1);

    // Split-K fp16 flash with in-kernel merge
    dim3 fgrid(2 * (SEQ / 128), NH);
    flash_split<<<fgrid, 128, FLASH_SMEM>>>(qh, kh, vt, p0, p1, m0, l0, m1, l1, ap);

    // Output projection
    dim3 ogrid(DIM / 128, SEQ / 128, 1);
    gemm_h<<<ogrid, 128, GSMEM>>>(ap, woh, woh, woh, out, out, out, cosT, sinT, 0);
}

// round 17
// speedup vs baseline: 1.7754x; 1.0166x over previous
#include <cuda_runtime.h>
#include <cuda_fp16.h>
#include <math.h>
#include <stdint.h>

#define SEQ 4096
#define DIM 1024
#define NH  16
#define HDIM 64

// Scratch
__device__ __half g_qh[NH * SEQ * HDIM];  // [h][s][hd] half, pre-scaled
__device__ __half g_kh[NH * SEQ * HDIM];  // [h][s][hd] half
__device__ __half g_vt[NH * SEQ * HDIM];  // [h][tile32][d64][key32] half (transposed)
__device__ __half g_att[SEQ * DIM];       // [s][d] half (merged attention out)
__device__ __half g_xh[SEQ * DIM];        // x as half
__device__ __half g_wqh[DIM * DIM];       // weights as half
__device__ __half g_wkh[DIM * DIM];
__device__ __half g_wvh[DIM * DIM];
__device__ __half g_woh[DIM * DIM];
// split-K partials (raw fp32)
__device__ float g_p0[SEQ * DIM];
__device__ float g_p1[SEQ * DIM];
__device__ float g_m0[NH * SEQ];
__device__ float g_l0[NH * SEQ];
__device__ float g_m1[NH * SEQ];
__device__ float g_l1[NH * SEQ];
// merge counters (zero-init; merger resets -> replay-safe)
__device__ int g_cnt[NH * (SEQ / 128)];

#define QSCALE (0.125f * 1.4426950408889634f)   // 1/sqrt(64) * log2(e)
#define MINIT  (-1.6e38f)
#define MMASK  (-3.2e38f)

__device__ __forceinline__ float ex2(float x) {
    float r;
    asm("ex2.approx.f32 %0, %1;" : "=f"(r) : "f"(x));
    return r;
}

// f16 m16n8k16, f32 accumulate
__device__ __forceinline__ void mma16h(float c[4],
    uint32_t a0, uint32_t a1, uint32_t a2, uint32_t a3,
    uint32_t b0, uint32_t b1)
{
    asm volatile(
        "mma.sync.aligned.m16n8k16.row.col.f32.f16.f16.f32 "
        "{%0,%1,%2,%3},{%4,%5,%6,%7},{%8,%9},{%0,%1,%2,%3};"
        : "+f"(c[0]), "+f"(c[1]), "+f"(c[2]), "+f"(c[3])
        : "r"(a0), "r"(a1), "r"(a2), "r"(a3), "r"(b0), "r"(b1));
}

__device__ __forceinline__ void ldsm4(uint32_t r[4], uint32_t addr) {
    asm volatile(
        "ldmatrix.sync.aligned.m8n8.x4.shared.b16 {%0,%1,%2,%3}, [%4];"
        : "=r"(r[0]), "=r"(r[1]), "=r"(r[2]), "=r"(r[3]) : "r"(addr));
}

__device__ __forceinline__ uint32_t pack_h2(float lo, float hi) {
    __half2 h = __floats2half2_rn(lo, hi);
    return *(uint32_t*)&h;
}

__device__ __forceinline__ void cpa16(uint32_t dst_smem, const void* src) {
    asm volatile("cp.async.cg.shared.global [%0], [%1], 16;"
                 :: "r"(dst_smem), "l"(src));
}
__device__ __forceinline__ void cpa_commit() {
    asm volatile("cp.async.commit_group;");
}
template<int N>
__device__ __forceinline__ void cpa_wait() {
    asm volatile("cp.async.wait_group %0;" :: "n"(N));
}

// ---------------------------------------------------------------------------
// Convert fp32 -> fp16
// ---------------------------------------------------------------------------
__global__ void cvt_h(const float* __restrict__ src, __half* __restrict__ dst,
                      int n4)
{
    for (int i = blockIdx.x * blockDim.x + threadIdx.x; i < n4;
         i += gridDim.x * blockDim.x) {
        float4 v = ((const float4*)src)[i];
        ((uint2*)dst)[i] = make_uint2(pack_h2(v.x, v.y), pack_h2(v.z, v.w));
    }
}

__global__ void cvt_h_w(const float* __restrict__ s0, __half* __restrict__ d0,
                        const float* __restrict__ s1, __half* __restrict__ d1,
                        const float* __restrict__ s2, __half* __restrict__ d2,
                        const float* __restrict__ s3, __half* __restrict__ d3,
                        int n4)
{
    const float* src; __half* dst;
    if (blockIdx.z == 0)      { src = s0; dst = d0; }
    else if (blockIdx.z == 1) { src = s1; dst = d1; }
    else if (blockIdx.z == 2) { src = s2; dst = d2; }
    else                      { src = s3; dst = d3; }
    for (int i = blockIdx.x * blockDim.x + threadIdx.x; i < n4;
         i += gridDim.x * blockDim.x) {
        float4 v = ((const float4*)src)[i];
        ((uint2*)dst)[i] = make_uint2(pack_h2(v.x, v.y), pack_h2(v.z, v.w));
    }
}

// ---------------------------------------------------------------------------
// FP16 GEMM (mma.sync m16n8k16 + ldmatrix), 256 threads (8 warps, 4x2),
// warp tile 32x64, BK=32 halves, 3-stage cp.async, ONE barrier per chunk.
// mode 0: plain f32 out; 1: Q RoPE+QSCALE half; 2: K RoPE half;
// 3: V half transposed per 32-key tile [h][t32][d64][key32].
// ---------------------------------------------------------------------------
#define GBK   32
#define GSA   20
#define GSTW  (128 * GSA)
#define GSTB  (2 * GSTW * 4)
#define GSMEM (3 * GSTB)

__global__ void __launch_bounds__(256, 2) gemm_h(
    const __half* __restrict__ A,
    const __half* __restrict__ W0, const __half* __restrict__ W1,
    const __half* __restrict__ W2,
    void* __restrict__ out0v, void* __restrict__ out1v,
    void* __restrict__ out2v,
    const float* __restrict__ cosT, const float* __restrict__ sinT,
    int mode0)
{
    extern __shared__ uint32_t gsm[];

    const __half* W; void* outv; int mode;
    if (blockIdx.z == 0)      { W = W0; outv = out0v; mode = mode0; }
    else if (blockIdx.z == 1) { W = W1; outv = out1v; mode = 2; }
    else                      { W = W2; outv = out2v; mode = 3; }

    const int tid  = threadIdx.x;
    const int lane = tid & 31;
    const int wid  = tid >> 5;     // 0..7
    const int wm   = wid >> 1;     // 0..3 (M: 32 rows each)
    const int wn   = wid & 1;      // 0..1 (N: 64 cols each)
    const int g4   = lane >> 2;
    const int t4   = lane & 3;

    const int mBase = blockIdx.y * 128;
    const int nBase = blockIdx.x * 128;

    const uint32_t smemu = (uint32_t)__cvta_generic_to_shared(gsm);

    // ldmatrix lane address components
    const int rowA = lane & 15;
    const int khA  = (lane >> 4) << 2;
    const int rowB = (lane & 7) + ((lane >> 4) << 3);
    const int khB  = ((lane >> 3) & 1) << 2;

    auto prefetch = [&](int s, int t) {
        const int koff = t * GBK;
        const uint32_t abase = smemu + s * GSTB;
        const uint32_t bbase = abase + GSTW * 4;
#pragma unroll
        for (int j = 0; j < 2; j++) {
            const int idx = tid + j * 256;       // 0..511
            const int r = idx >> 2, c16 = idx & 3;
            cpa16(abase + (r * GSA + c16 * 4) * 4,
                  A + (size_t)(mBase + r) * DIM + koff + c16 * 8);
            cpa16(bbase + (r * GSA + c16 * 4) * 4,
                  W + (size_t)(nBase + r) * DIM + koff + c16 * 8);
        }
    };

    float c[2][8][4];
#pragma unroll
    for (int mt = 0; mt < 2; mt++)
#pragma unroll
        for (int nt = 0; nt < 8; nt++)
#pragma unroll
            for (int i = 0; i < 4; i++) c[mt][nt][i] = 0.f;

    const int NT = DIM / GBK;
    prefetch(0, 0); cpa_commit();
    prefetch(1, 1); cpa_commit();

    for (int t = 0; t < NT; t++) {
        if (t + 1 < NT) cpa_wait<1>(); else cpa_wait<0>();
        __syncthreads();

        if (t + 2 < NT) { prefetch((t + 2) % 3, t + 2); cpa_commit(); }

        const uint32_t abase = smemu + (t % 3) * GSTB;
        const uint32_t bbase = abase + GSTW * 4;
#pragma unroll
        for (int ks = 0; ks < 2; ks++) {
            uint32_t af[2][4];
#pragma unroll
            for (int mt = 0; mt < 2; mt++)
                ldsm4(af[mt], abase +
                      ((wm * 32 + mt * 16 + rowA) * GSA + ks * 8 + khA) * 4);
#pragma unroll
            for (int ntp = 0; ntp < 4; ntp++) {
                uint32_t bb[4];
                ldsm4(bb, bbase +
                      ((wn * 64 + ntp * 16 + rowB) * GSA + ks * 8 + khB) * 4);
#pragma unroll
                for (int mt = 0; mt < 2; mt++) {
                    mma16h(c[mt][2 * ntp],     af[mt][0], af[mt][1], af[mt][2], af[mt][3], bb[0], bb[1]);
                    mma16h(c[mt][2 * ntp + 1], af[mt][0], af[mt][1], af[mt][2], af[mt][3], bb[2], bb[3]);
                }
            }
        }
    }

    // Epilogue
#pragma unroll
    for (int mt = 0; mt < 2; mt++) {
        const int r0 = mBase + wm * 32 + mt * 16 + g4;
#pragma unroll
        for (int nt = 0; nt < 8; nt++) {
            const int colg = nBase + wn * 64 + nt * 8 + (t4 << 1);
            const float* cc = c[mt][nt];
            if (mode == 0) {
                float* out = (float*)outv;
                *(float2*)(out + (size_t)r0 * DIM + colg)       = make_float2(cc[0], cc[1]);
                *(float2*)(out + (size_t)(r0 + 8) * DIM + colg) = make_float2(cc[2], cc[3]);
                continue;
            }
            __half* outh = (__half*)outv;
            const int head = colg >> 6;
            const int hd   = colg & 63;
            const int f    = hd >> 1;
#pragma unroll
            for (int h = 0; h < 2; h++) {
                const int row = r0 + h * 8;
                float e = cc[h * 2 + 0], o = cc[h * 2 + 1];
                if (mode != 3) {
                    const float cth = cosT[row * 32 + f];
                    const float sth = sinT[row * 32 + f];
                    float re = e * cth - o * sth;
                    float ro = e * sth + o * cth;
                    if (mode == 1) { re *= QSCALE; ro *= QSCALE; }
                    *(uint32_t*)(outh + ((size_t)head * SEQ + row) * HDIM + hd) =
                        pack_h2(re, ro);
                } else {
                    const int t32 = row >> 5, key = row & 31;
                    __half* vt = outh + (size_t)head * SEQ * HDIM + t32 * 2048;
                    vt[hd * 32 + key]       = __float2half_rn(e);
                    vt[(hd + 1) * 32 + key] = __float2half_rn(o);
                }
            }
        }
    }
}

// ---------------------------------------------------------------------------
// Split-K FP16 flash attention with in-kernel merge, ldmatrix operand loads.
// (unchanged from R16)
// ---------------------------------------------------------------------------
#define KT  32
#define KRS 36
#define VRS 28
#define KTILE_SW (KT * KRS)
#define VTILE_SW (HDIM * VRS)
#define STG_W (KTILE_SW + VTILE_SW)
#define FLASH_SMEM (2 * STG_W * (int)sizeof(uint32_t))

__global__ void __launch_bounds__(128, 3) flash_split(
    const __half* __restrict__ Q, const __half* __restrict__ K,
    const __half* __restrict__ V,
    float* __restrict__ p0, float* __restrict__ p1,
    float* __restrict__ gm0, float* __restrict__ gl0,
    float* __restrict__ gm1, float* __restrict__ gl1,
    __half* __restrict__ att)
{
    extern __shared__ uint32_t fsm[];

    const int tid  = threadIdx.x;
    const int lane = tid & 31;
    const int wid  = tid >> 5;
    const int g4   = lane >> 2;
    const int t4   = lane & 3;

    const int enc  = gridDim.x - 1 - blockIdx.x;
    const int qblk = enc >> 1;
    const int split = enc & 1;
    const int head = blockIdx.y;

    float* part = split ? p1 : p0;
    float* gm   = split ? gm1 : gm0;
    float* gl   = split ? gl1 : gl0;

    const uint32_t smemu = (uint32_t)__cvta_generic_to_shared(fsm);
    const __half* Kh0 = K + (size_t)head * SEQ * HDIM;
    const __half* Vt0 = V + (size_t)head * SEQ * HDIM;

    const int rowB = (lane & 7) + ((lane >> 4) << 3);
    const int khB  = ((lane >> 3) & 1) << 2;

    auto prefetch = [&](int buf, int kb) {
        const uint32_t base = smemu + buf * STG_W * 4;
        const __half* Kt = Kh0 + (size_t)kb * 2048;
        const __half* Vt = Vt0 + (size_t)kb * 2048;
#pragma unroll
        for (int j = 0; j < 2; j++) {
            const int idx = tid + j * 128;
            const int r = idx >> 3, ck = idx & 7;
            cpa16(base + (r * KRS + ck * 4) * 4, Kt + r * HDIM + ck * 8);
            const int rv = idx >> 2, cv = idx & 3;
            cpa16(base + (KTILE_SW + rv * VRS + cv * 4) * 4, Vt + rv * KT + cv * 8);
        }
    };

    const int half = 2 * (qblk + 1);
    const int t0 = split * half;
    const int t1 = t0 + half;

    prefetch(0, t0); cpa_commit();
    prefetch(1, t0 + 1); cpa_commit();

    uint32_t qf[4][2][4];
    {
        const __half* Qh = Q + ((size_t)head * SEQ + qblk * 128 + wid * 32) * HDIM;
#pragma unroll
        for (int ks = 0; ks < 4; ks++)
#pragma unroll
            for (int mh = 0; mh < 2; mh++) {
                const int row0 = mh * 16 + g4;
                const int d0 = ks * 16 + t4 * 2;
                qf[ks][mh][0] = *(const uint32_t*)(Qh + row0 * HDIM + d0);
                qf[ks][mh][1] = *(const uint32_t*)(Qh + (row0 + 8) * HDIM + d0);
                qf[ks][mh][2] = *(const uint32_t*)(Qh + row0 * HDIM + d0 + 8);
                qf[ks][mh][3] = *(const uint32_t*)(Qh + (row0 + 8) * HDIM + d0 + 8);
            }
    }

    float o[2][8][4];
#pragma unroll
    for (int mh = 0; mh < 2; mh++)
#pragma unroll
        for (int nt = 0; nt < 8; nt++)
#pragma unroll
            for (int i = 0; i < 4; i++) o[mh][nt][i] = 0.f;

    float m[2][2], l[2][2];
#pragma unroll
    for (int mh = 0; mh < 2; mh++) {
        m[mh][0] = MINIT; m[mh][1] = MINIT;
        l[mh][0] = 0.f;   l[mh][1] = 0.f;
    }

    for (int kb = t0; kb < t1; kb++) {
        if (kb + 1 < t1) cpa_wait<1>(); else cpa_wait<0>();
        __syncthreads();

        const uint32_t kbase = smemu + (kb & 1) * STG_W * 4;
        const uint32_t vbase = kbase + KTILE_SW * 4;

        float sc[2][4][4];
#pragma unroll
        for (int mh = 0; mh < 2; mh++)
#pragma unroll
            for (int nt = 0; nt < 4; nt++)
#pragma unroll
                for (int i = 0; i < 4; i++) sc[mh][nt][i] = 0.f;

#pragma unroll
        for (int ks = 0; ks < 4; ks++) {
#pragma unroll
            for (int ntp = 0; ntp < 2; ntp++) {
                uint32_t bb[4];
                ldsm4(bb, kbase + ((ntp * 16 + rowB) * KRS + ks * 8 + khB) * 4);
                mma16h(sc[0][2 * ntp],     qf[ks][0][0], qf[ks][0][1], qf[ks][0][2], qf[ks][0][3], bb[0], bb[1]);
                mma16h(sc[1][2 * ntp],     qf[ks][1][0], qf[ks][1][1], qf[ks][1][2], qf[ks][1][3], bb[0], bb[1]);
                mma16h(sc[0][2 * ntp + 1], qf[ks][0][0], qf[ks][0][1], qf[ks][0][2], qf[ks][0][3], bb[2], bb[3]);
                mma16h(sc[1][2 * ntp + 1], qf[ks][1][0], qf[ks][1][1], qf[ks][1][2], qf[ks][1][3], bb[2], bb[3]);
            }
        }

        if (kb >= 4 * qblk) {
#pragma unroll
            for (int mh = 0; mh < 2; mh++) {
                const int r0 = qblk * 128 + wid * 32 + mh * 16 + g4;
                const int r1 = r0 + 8;
#pragma unroll
                for (int nt = 0; nt < 4; nt++) {
                    const int col = kb * KT + nt * 8 + (t4 << 1);
                    if (col > r0)     sc[mh][nt][0] = MMASK;
                    if (col + 1 > r0) sc[mh][nt][1] = MMASK;
                    if (col > r1)     sc[mh][nt][2] = MMASK;
                    if (col + 1 > r1) sc[mh][nt][3] = MMASK;
                }
            }
        }

        float corr[2][2];
#pragma unroll
        for (int mh = 0; mh < 2; mh++) {
            float mx0 = MMASK, mx1 = MMASK;
#pragma unroll
            for (int nt = 0; nt < 4; nt++) {
                mx0 = fmaxf(mx0, fmaxf(sc[mh][nt][0], sc[mh][nt][1]));
                mx1 = fmaxf(mx1, fmaxf(sc[mh][nt][2], sc[mh][nt][3]));
            }
            mx0 = fmaxf(mx0, __shfl_xor_sync(0xffffffffu, mx0, 1));
            mx0 = fmaxf(mx0, __shfl_xor_sync(0xffffffffu, mx0, 2));
            mx1 = fmaxf(mx1, __shfl_xor_sync(0xffffffffu, mx1, 1));
            mx1 = fmaxf(mx1, __shfl_xor_sync(0xffffffffu, mx1, 2));

            const float mn0 = fmaxf(m[mh][0], mx0);
            const float mn1 = fmaxf(m[mh][1], mx1);
            corr[mh][0] = ex2(m[mh][0] - mn0);
            corr[mh][1] = ex2(m[mh][1] - mn1);
            m[mh][0] = mn0; m[mh][1] = mn1;

            float ls0 = 0.f, ls1 = 0.f;
#pragma unroll
            for (int nt = 0; nt < 4; nt++) {
                sc[mh][nt][0] = ex2(sc[mh][nt][0] - mn0);
                sc[mh][nt][1] = ex2(sc[mh][nt][1] - mn0);
                sc[mh][nt][2] = ex2(sc[mh][nt][2] - mn1);
                sc[mh][nt][3] = ex2(sc[mh][nt][3] - mn1);
                ls0 += sc[mh][nt][0] + sc[mh][nt][1];
                ls1 += sc[mh][nt][2] + sc[mh][nt][3];
            }
            ls0 += __shfl_xor_sync(0xffffffffu, ls0, 1);
            ls0 += __shfl_xor_sync(0xffffffffu, ls0, 2);
            ls1 += __shfl_xor_sync(0xffffffffu, ls1, 1);
            ls1 += __shfl_xor_sync(0xffffffffu, ls1, 2);
            l[mh][0] = l[mh][0] * corr[mh][0] + ls0;
            l[mh][1] = l[mh][1] * corr[mh][1] + ls1;

#pragma unroll
            for (int nt = 0; nt < 8; nt++) {
                o[mh][nt][0] *= corr[mh][0]; o[mh][nt][1] *= corr[mh][0];
                o[mh][nt][2] *= corr[mh][1]; o[mh][nt][3] *= corr[mh][1];
            }
        }

#pragma unroll
        for (int ks = 0; ks < 2; ks++) {
            uint32_t pa[2][4];
#pragma unroll
            for (int mh = 0; mh < 2; mh++) {
                pa[mh][0] = pack_h2(sc[mh][2 * ks][0],     sc[mh][2 * ks][1]);
                pa[mh][1] = pack_h2(sc[mh][2 * ks][2],     sc[mh][2 * ks][3]);
                pa[mh][2] = pack_h2(sc[mh][2 * ks + 1][0], sc[mh][2 * ks + 1][1]);
                pa[mh][3] = pack_h2(sc[mh][2 * ks + 1][2], sc[mh][2 * ks + 1][3]);
            }
#pragma unroll
            for (int ntp = 0; ntp < 4; ntp++) {
                uint32_t bb[4];
                ldsm4(bb, vbase + ((ntp * 16 + rowB) * VRS + ks * 8 + khB) * 4);
                mma16h(o[0][2 * ntp],     pa[0][0], pa[0][1], pa[0][2], pa[0][3], bb[0], bb[1]);
                mma16h(o[1][2 * ntp],     pa[1][0], pa[1][1], pa[1][2], pa[1][3], bb[0], bb[1]);
                mma16h(o[0][2 * ntp + 1], pa[0][0], pa[0][1], pa[0][2], pa[0][3], bb[2], bb[3]);
                mma16h(o[1][2 * ntp + 1], pa[1][0], pa[1][1], pa[1][2], pa[1][3], bb[2], bb[3]);
            }
        }

        __syncthreads();
        if (kb + 2 < t1) { prefetch(kb & 1, kb + 2); cpa_commit(); }
    }

#pragma unroll
    for (int mh = 0; mh < 2; mh++) {
        const int r0 = qblk * 128 + wid * 32 + mh * 16 + g4;
#pragma unroll
        for (int nt = 0; nt < 8; nt++) {
            const int col = head * HDIM + nt * 8 + (t4 << 1);
            *(float2*)(part + (size_t)r0 * DIM + col) =
                make_float2(o[mh][nt][0], o[mh][nt][1]);
            *(float2*)(part + (size_t)(r0 + 8) * DIM + col) =
                make_float2(o[mh][nt][2], o[mh][nt][3]);
        }
        if (t4 == 0) {
            gm[head * SEQ + r0]     = m[mh][0];
            gl[head * SEQ + r0]     = l[mh][0];
            gm[head * SEQ + r0 + 8] = m[mh][1];
            gl[head * SEQ + r0 + 8] = l[mh][1];
        }
    }

    __threadfence();
    __syncthreads();
    if (tid == 0) {
        const int old = atomicAdd(&g_cnt[head * (SEQ / 128) + qblk], 1);
        ((volatile int*)fsm)[0] = old;
    }
    __syncthreads();
    const int old = ((volatile int*)fsm)[0];
    if (old != 1) return;
    __threadfence();
    if (tid == 0) g_cnt[head * (SEQ / 128) + qblk] = 0;

    const float* po  = split ? p0 : p1;
    const float* gmo = split ? gm0 : gm1;
    const float* glo = split ? gl0 : gl1;

#pragma unroll
    for (int mh = 0; mh < 2; mh++) {
        const int r0 = qblk * 128 + wid * 32 + mh * 16 + g4;
#pragma unroll
        for (int rh = 0; rh < 2; rh++) {
            const int row = r0 + rh * 8;
            const float mOwn = m[mh][rh], lOwn = l[mh][rh];
            const float mOth = gmo[head * SEQ + row];
            const float lOth = glo[head * SEQ + row];
            const float mA = split ? mOth : mOwn;
            const float lA = split ? lOth : lOwn;
            const float mB = split ? mOwn : mOth;
            const float lB = split ? lOwn : lOth;
            const float ms = fmaxf(mA, mB);
            const float wA = ex2(mA - ms), wB = ex2(mB - ms);
            const float inv = 1.f / (lA * wA + lB * wB);
            const float wOwn = split ? wB : wA;
            const float wOth = split ? wA : wB;
#pragma unroll
            for (int nt = 0; nt < 8; nt++) {
                const int col = head * HDIM + nt * 8 + (t4 << 1);
                const float2 ov = *(const float2*)(po + (size_t)row * DIM + col);
                const float x0 = (o[mh][nt][rh * 2 + 0] * wOwn + ov.x * wOth) * inv;
                const float x1 = (o[mh][nt][rh * 2 + 1] * wOwn + ov.y * wOth) * inv;
                *(uint32_t*)(att + (size_t)row * DIM + col) = pack_h2(x0, x1);
            }
        }
    }
}

// ---------------------------------------------------------------------------
// Launch
// ---------------------------------------------------------------------------
extern "C" void kernel_launch(void* const* d_in, const int* in_sizes, int n_in,
                              void* d_out, int out_size)
{
    const float* x    = (const float*)d_in[0];
    const float* cosT = (const float*)d_in[1];
    const float* sinT = (const float*)d_in[2];
    const float* wq   = (const float*)d_in[4];
    const float* wk   = (const float*)d_in[5];
    const float* wv   = (const float*)d_in[6];
    const float* wo   = (const float*)d_in[7];
    float* out = (float*)d_out;

    float *p0, *p1, *m0, *l0, *m1, *l1;
    __half *qh, *kh, *vt, *ap, *xh, *wqh, *wkh, *wvh, *woh;
    cudaGetSymbolAddress((void**)&qh, g_qh);
    cudaGetSymbolAddress((void**)&kh, g_kh);
    cudaGetSymbolAddress((void**)&vt, g_vt);
    cudaGetSymbolAddress((void**)&ap, g_att);
    cudaGetSymbolAddress((void**)&xh, g_xh);
    cudaGetSymbolAddress((void**)&wqh, g_wqh);
    cudaGetSymbolAddress((void**)&wkh, g_wkh);
    cudaGetSymbolAddress((void**)&wvh, g_wvh);
    cudaGetSymbolAddress((void**)&woh, g_woh);
    cudaGetSymbolAddress((void**)&p0, g_p0);
    cudaGetSymbolAddress((void**)&p1, g_p1);
    cudaGetSymbolAddress((void**)&m0, g_m0);
    cudaGetSymbolAddress((void**)&l0, g_l0);
    cudaGetSymbolAddress((void**)&m1, g_m1);
    cudaGetSymbolAddress((void**)&l1, g_l1);

    cudaFuncSetAttribute(flash_split,
                         cudaFuncAttributeMaxDynamicSharedMemorySize, FLASH_SMEM);
    cudaFuncSetAttribute(gemm_h,
                         cudaFuncAttributeMaxDynamicSharedMemorySize, GSMEM);

    // Convert inputs to fp16 once
    cvt_h<<<512, 256>>>(x, xh, SEQ * DIM / 4);
    dim3 wgrid(128, 1, 4);
    cvt_h_w<<<wgrid, 256>>>(wq, wqh, wk, wkh, wv, wvh, wo, woh, DIM * DIM / 4);

    // Fused QKV projections (256 threads, 8 warps)
    dim3 ggrid(DIM / 128, SEQ / 128, 3);
    gemm_h<<<ggrid, 256, GSMEM>>>(xh, wqh, wkh, wvh, qh, kh, vt, cosT, sinT, 1);

    // Split-K fp16 flash with in-kernel merge
    dim3 fgrid(2 * (SEQ / 128), NH);
    flash_split<<<fgrid, 128, FLASH_SMEM>>>(qh, kh, vt, p0, p1, m0, l0, m1, l1, ap);

    // Output projection
    dim3 ogrid(DIM / 128, SEQ / 128, 1);
    gemm_h<<<ogrid, 256, GSMEM>>>(ap, woh, woh, woh, out, out, out, cosT, sinT, 0);
}